// round 9
// baseline (speedup 1.0000x reference)
#include <cuda_runtime.h>
#include <cuda_bf16.h>
#include <cstdint>

#define H       128
#define NBR     10
#define AF      35
#define BF      40            // ATOM_FDIM + BOND_FDIM
#define N_ATOMS 100000
#define N_BONDS 220000
#define N_MESS  20000
#define N_MOLS  2000
#define MSG_ROWS (N_MESS + N_BONDS)
#define TM      64            // rows per block tile (SIMT binput)
#define TB      256

// bond mma kernel tiling
#define BMT     64            // rows per tile
#define NT_BOND ((N_BONDS + BMT - 1) / BMT)   // 3438 tiles
#define ASTR    136           // A row stride (bf16), conflict-free fragments
// atom mma kernel tiling
#define NT_ATOM ((N_ATOMS + 63) / 64)         // 1563 tiles
#define ASTRA   184           // A row stride (bf16), conflict-free fragments
#define NS_A    11            // k-steps for atom
#define PGRID   304           // persistent grid: 2 CTAs x 152 SMs

// ---- scratch (device globals: allocation-free kernel_launch) ----
__device__ float g_msgA[(size_t)MSG_ROWS * H];
__device__ float g_msgB[(size_t)MSG_ROWS * H];
__device__ float g_binput[(size_t)N_BONDS * H];
__device__ float g_atomh[(size_t)N_ATOMS * H];
// W_h fragments: [kstep 8][ntile 16][lane 32] uint2, hi & lo planes
__device__ uint2 g_wf_hi[8 * 16 * 32];
__device__ uint2 g_wf_lo[8 * 16 * 32];
// W_o (reordered+padded) fragments: [kstep 11][ntile 16][lane 32]
__device__ uint2 g_wfo_hi[NS_A * 16 * 32];
__device__ uint2 g_wfo_lo[NS_A * 16 * 32];

#define MMA16816(c, a0, a1, a2, a3, b0, b1) \
    asm volatile("mma.sync.aligned.m16n8k16.row.col.f32.bf16.bf16.f32 " \
        "{%0,%1,%2,%3}, {%4,%5,%6,%7}, {%8,%9}, {%0,%1,%2,%3};" \
        : "+f"((c)[0]), "+f"((c)[1]), "+f"((c)[2]), "+f"((c)[3]) \
        : "r"(a0), "r"(a1), "r"(a2), "r"(a3), "r"(b0), "r"(b1))

__device__ __forceinline__ unsigned short bf16hi(float v) {
    return __bfloat16_as_ushort(__float2bfloat16_rn(v));
}
__device__ __forceinline__ void split2(float v, unsigned short& h, unsigned short& l) {
    h = bf16hi(v);
    l = bf16hi(v - __bfloat162float(__ushort_as_bfloat16(h)));
}

// ---------------------------------------------------------------
__global__ void tree_copy_kernel(const float* __restrict__ tree) {
    int i = blockIdx.x * blockDim.x + threadIdx.x;
    int n4 = N_MESS * H / 4;
    if (i < n4) {
        float4 v = ((const float4*)tree)[i];
        ((float4*)g_msgA)[i] = v;
        ((float4*)g_msgB)[i] = v;
    }
}

// ---------------------------------------------------------------
// W_h [k][n] -> bf16 hi/lo B-fragments (m16n8k16):
// i = s*512 + t*32 + lane; g=lane>>2, tig=lane&3; n=t*8+g; k0=s*16+tig*2
__global__ void prep_w_kernel(const float* __restrict__ W_h) {
    int i = blockIdx.x * blockDim.x + threadIdx.x;
    if (i >= 8 * 16 * 32) return;
    int lane = i & 31, t = (i >> 5) & 15, s = i >> 9;
    int g = lane >> 2, tig = lane & 3;
    int n = t * 8 + g;
    int k0 = s * 16 + tig * 2;
    float w[4] = { W_h[(k0 + 0) * H + n], W_h[(k0 + 1) * H + n],
                   W_h[(k0 + 8) * H + n], W_h[(k0 + 9) * H + n] };
    unsigned short h[4], l[4];
#pragma unroll
    for (int j = 0; j < 4; j++) split2(w[j], h[j], l[j]);
    g_wf_hi[i] = make_uint2((uint32_t)h[0] | ((uint32_t)h[1] << 16),
                            (uint32_t)h[2] | ((uint32_t)h[3] << 16));
    g_wf_lo[i] = make_uint2((uint32_t)l[0] | ((uint32_t)l[1] << 16),
                            (uint32_t)l[2] | ((uint32_t)l[3] << 16));
}

// W_o reordered (A col k: k<128 -> W_o row 35+k; 128..162 -> row k-128; else 0)
__device__ __forceinline__ float wo_val(const float* W_o, int k, int n) {
    if (k < 128)  return W_o[(size_t)(35 + k) * H + n];
    if (k < 163)  return W_o[(size_t)(k - 128) * H + n];
    return 0.f;
}
__global__ void prep_wo_kernel(const float* __restrict__ W_o) {
    int i = blockIdx.x * blockDim.x + threadIdx.x;
    if (i >= NS_A * 16 * 32) return;
    int lane = i & 31, t = (i >> 5) & 15, s = i >> 9;
    int g = lane >> 2, tig = lane & 3;
    int n = t * 8 + g;
    int k0 = s * 16 + tig * 2;
    float w[4] = { wo_val(W_o, k0 + 0, n), wo_val(W_o, k0 + 1, n),
                   wo_val(W_o, k0 + 8, n), wo_val(W_o, k0 + 9, n) };
    unsigned short h[4], l[4];
#pragma unroll
    for (int j = 0; j < 4; j++) split2(w[j], h[j], l[j]);
    g_wfo_hi[i] = make_uint2((uint32_t)h[0] | ((uint32_t)h[1] << 16),
                             (uint32_t)h[2] | ((uint32_t)h[3] << 16));
    g_wfo_lo[i] = make_uint2((uint32_t)l[0] | ((uint32_t)l[1] << 16),
                             (uint32_t)l[2] | ((uint32_t)l[3] << 16));
}

// ---------------------------------------------------------------
// binput = fbonds @ W_i ; msgA graph part = relu(binput)   (SIMT)
__global__ void binput_kernel(const float* __restrict__ fbonds,
                              const float* __restrict__ W_i) {
    extern __shared__ float sm[];
    float* Asm = sm;             // [TM][BF]
    float* Wsm = sm + TM * BF;   // [BF][H]
    int m0 = blockIdx.x * TM;
    int tid = threadIdx.x;
    int warp = tid >> 5, lane = tid & 31;

    for (int i = tid * 4; i < BF * H; i += TB * 4)
        *(float4*)&Wsm[i] = *(const float4*)&W_i[i];
    for (int i = tid; i < TM * BF; i += TB) {
        int r = i / BF, c = i % BF;
        int m = m0 + r;
        Asm[i] = (m < N_BONDS) ? __ldcs(&fbonds[(size_t)m * BF + c]) : 0.f;
    }
    __syncthreads();

    float acc[8][4];
#pragma unroll
    for (int i = 0; i < 8; i++)
#pragma unroll
        for (int j = 0; j < 4; j++) acc[i][j] = 0.f;
    int n0 = lane * 4;
#pragma unroll
    for (int kk = 0; kk < BF; kk += 4) {
        float4 b0 = *(float4*)&Wsm[(kk + 0) * H + n0];
        float4 b1 = *(float4*)&Wsm[(kk + 1) * H + n0];
        float4 b2 = *(float4*)&Wsm[(kk + 2) * H + n0];
        float4 b3 = *(float4*)&Wsm[(kk + 3) * H + n0];
#pragma unroll
        for (int i = 0; i < 8; i++) {
            float4 a = *(float4*)&Asm[(warp * 8 + i) * BF + kk];
            acc[i][0] += a.x * b0.x + a.y * b1.x + a.z * b2.x + a.w * b3.x;
            acc[i][1] += a.x * b0.y + a.y * b1.y + a.z * b2.y + a.w * b3.y;
            acc[i][2] += a.x * b0.z + a.y * b1.z + a.z * b2.z + a.w * b3.z;
            acc[i][3] += a.x * b0.w + a.y * b1.w + a.z * b2.w + a.w * b3.w;
        }
    }
    float* graphA = g_msgA + (size_t)N_MESS * H;
#pragma unroll
    for (int i = 0; i < 8; i++) {
        int m = m0 + warp * 8 + i;
        if (m < N_BONDS) {
            float4 v = make_float4(acc[i][0], acc[i][1], acc[i][2], acc[i][3]);
            __stcs((float4*)&g_binput[(size_t)m * H + n0], v);
            float4 r = make_float4(fmaxf(v.x, 0.f), fmaxf(v.y, 0.f),
                                   fmaxf(v.z, 0.f), fmaxf(v.w, 0.f));
            *(float4*)&graphA[(size_t)m * H + n0] = r;
        }
    }
}

// ---------------------------------------------------------------
// bond iter: dst = relu(binput + gathersum(src)@W_h)
// PERSISTENT: each CTA stages W fragments ONCE, then grid-strides over
// 64-row tiles. Removes 220 MB/iter of W re-staging L2 traffic that was
// evicting the gather's src working set. dst stores default-cached (it is
// next iter's gather src); binput reads streamed (no reuse this iter).
__global__ void __launch_bounds__(256, 2)
bond_mma_kernel(const float* __restrict__ src_msg,
                float* __restrict__ dst_graph,
                const int* __restrict__ bgraph) {
    extern __shared__ char smem[];
    __nv_bfloat16* Ahi = (__nv_bfloat16*)smem;            // [BMT][ASTR]
    __nv_bfloat16* Alo = Ahi + BMT * ASTR;
    uint2* WH = (uint2*)(Alo + BMT * ASTR);               // [4096]
    uint2* WL = WH + 4096;

    int tid = threadIdx.x, warp = tid >> 5, lane = tid & 31;

    // stage W fragments once (64 KB = 2 x 2048 uint4)
    {
        const uint4* sh = (const uint4*)g_wf_hi;
        const uint4* sl = (const uint4*)g_wf_lo;
        uint4* dh = (uint4*)WH;
        uint4* dl = (uint4*)WL;
        for (int i = tid; i < 2048; i += 256) { dh[i] = sh[i]; dl[i] = sl[i]; }
    }

    int g = lane >> 2, tig = lane & 3;

    for (int tile = blockIdx.x; tile < NT_BOND; tile += gridDim.x) {
        int m0 = tile * BMT;
        __syncthreads();   // W visible (1st iter); A smem free of readers (rest)

        // gather: warp -> 8 rows, lane -> cols [4l, 4l+4)
#pragma unroll
        for (int i = 0; i < 8; i++) {
            int r = warp * 8 + i;
            int m = m0 + r;
            float4 acc = make_float4(0.f, 0.f, 0.f, 0.f);
            if (m < N_BONDS) {
                const int* bg = &bgraph[m * NBR];
#pragma unroll
                for (int nb = 0; nb < NBR; nb++) {
                    int idx = __ldg(&bg[nb]);
                    float4 v = *(const float4*)&src_msg[(size_t)idx * H + lane * 4];
                    acc.x += v.x; acc.y += v.y; acc.z += v.z; acc.w += v.w;
                }
            }
            float a[4] = {acc.x, acc.y, acc.z, acc.w};
            unsigned short hs[4], ls[4];
#pragma unroll
            for (int j = 0; j < 4; j++) split2(a[j], hs[j], ls[j]);
            *(uint2*)&Ahi[r * ASTR + lane * 4] =
                make_uint2((uint32_t)hs[0] | ((uint32_t)hs[1] << 16),
                           (uint32_t)hs[2] | ((uint32_t)hs[3] << 16));
            *(uint2*)&Alo[r * ASTR + lane * 4] =
                make_uint2((uint32_t)ls[0] | ((uint32_t)ls[1] << 16),
                           (uint32_t)ls[2] | ((uint32_t)ls[3] << 16));
        }
        __syncthreads();

        // MMA: warp (w&3) -> row half, (w>>2) -> col half
        int r0 = (warp & 3) * 16 + g;
        int tbase = (warp >> 2) * 8;
        float c[8][4];
#pragma unroll
        for (int t = 0; t < 8; t++)
#pragma unroll
            for (int j = 0; j < 4; j++) c[t][j] = 0.f;

#pragma unroll
        for (int s = 0; s < 8; s++) {
            int k0 = s * 16 + tig * 2;
            uint32_t ah0 = *(const uint32_t*)&Ahi[(r0    ) * ASTR + k0];
            uint32_t ah1 = *(const uint32_t*)&Ahi[(r0 + 8) * ASTR + k0];
            uint32_t ah2 = *(const uint32_t*)&Ahi[(r0    ) * ASTR + k0 + 8];
            uint32_t ah3 = *(const uint32_t*)&Ahi[(r0 + 8) * ASTR + k0 + 8];
            uint32_t al0 = *(const uint32_t*)&Alo[(r0    ) * ASTR + k0];
            uint32_t al1 = *(const uint32_t*)&Alo[(r0 + 8) * ASTR + k0];
            uint32_t al2 = *(const uint32_t*)&Alo[(r0    ) * ASTR + k0 + 8];
            uint32_t al3 = *(const uint32_t*)&Alo[(r0 + 8) * ASTR + k0 + 8];
#pragma unroll
            for (int t = 0; t < 8; t++) {
                uint2 bh = WH[s * 512 + (tbase + t) * 32 + lane];
                uint2 bl = WL[s * 512 + (tbase + t) * 32 + lane];
                MMA16816(c[t], ah0, ah1, ah2, ah3, bh.x, bh.y);
                MMA16816(c[t], ah0, ah1, ah2, ah3, bl.x, bl.y);
                MMA16816(c[t], al0, al1, al2, al3, bh.x, bh.y);
            }
        }

        // epilogue: binput streamed in, dst default-cached (next iter's src)
        int mA = m0 + r0;
        int mB = mA + 8;
        int ncol0 = (warp >> 2) * 64 + tig * 2;
#pragma unroll
        for (int t = 0; t < 8; t++) {
            int n0 = ncol0 + t * 8;
            if (mA < N_BONDS) {
                float2 bi = __ldcs((const float2*)&g_binput[(size_t)mA * H + n0]);
                float2 o = make_float2(fmaxf(bi.x + c[t][0], 0.f),
                                       fmaxf(bi.y + c[t][1], 0.f));
                *(float2*)&dst_graph[(size_t)mA * H + n0] = o;
            }
            if (mB < N_BONDS) {
                float2 bi = __ldcs((const float2*)&g_binput[(size_t)mB * H + n0]);
                float2 o = make_float2(fmaxf(bi.x + c[t][2], 0.f),
                                       fmaxf(bi.y + c[t][3], 0.f));
                *(float2*)&dst_graph[(size_t)mB * H + n0] = o;
            }
        }
    }
}

// ---------------------------------------------------------------
// atom: g_atomh = relu([nei(128)|fatoms(35)|pad] @ Wo_frag + b_o)  via mma
// PERSISTENT: Wo hi staged once; Wo lo via __ldg (L2).
__global__ void __launch_bounds__(256, 2)
atom_mma_kernel(const float* __restrict__ src_msg,
                const int* __restrict__ agraph,
                const float* __restrict__ fatoms,
                const float* __restrict__ b_o) {
    extern __shared__ char smem[];
    __nv_bfloat16* Ahi = (__nv_bfloat16*)smem;            // [64][ASTRA]
    __nv_bfloat16* Alo = Ahi + 64 * ASTRA;
    uint2* WH = (uint2*)(Alo + 64 * ASTRA);               // [NS_A*512]

    int tid = threadIdx.x, warp = tid >> 5, lane = tid & 31;

    // stage Wo hi fragments once: NS_A*512 uint2 = 45056 B = 2816 uint4
    {
        const uint4* sh = (const uint4*)g_wfo_hi;
        uint4* dh = (uint4*)WH;
        for (int i = tid; i < 2816; i += 256) dh[i] = sh[i];
    }

    int g = lane >> 2, tig = lane & 3;

    for (int tile = blockIdx.x; tile < NT_ATOM; tile += gridDim.x) {
        int m0 = tile * 64;
        __syncthreads();

        // nei gather into cols [0,128)
#pragma unroll
        for (int i = 0; i < 8; i++) {
            int r = warp * 8 + i;
            int m = m0 + r;
            float4 acc = make_float4(0.f, 0.f, 0.f, 0.f);
            if (m < N_ATOMS) {
                const int* ag = &agraph[m * NBR];
#pragma unroll
                for (int nb = 0; nb < NBR; nb++) {
                    int idx = __ldg(&ag[nb]);
                    float4 v = *(const float4*)&src_msg[(size_t)idx * H + lane * 4];
                    acc.x += v.x; acc.y += v.y; acc.z += v.z; acc.w += v.w;
                }
            }
            float a[4] = {acc.x, acc.y, acc.z, acc.w};
            unsigned short hs[4], ls[4];
#pragma unroll
            for (int j = 0; j < 4; j++) split2(a[j], hs[j], ls[j]);
            *(uint2*)&Ahi[r * ASTRA + lane * 4] =
                make_uint2((uint32_t)hs[0] | ((uint32_t)hs[1] << 16),
                           (uint32_t)hs[2] | ((uint32_t)hs[3] << 16));
            *(uint2*)&Alo[r * ASTRA + lane * 4] =
                make_uint2((uint32_t)ls[0] | ((uint32_t)ls[1] << 16),
                           (uint32_t)ls[2] | ((uint32_t)ls[3] << 16));
        }
        // fatoms into cols [128,163), zero pad [163,176)
        for (int i = tid; i < 64 * 48; i += 256) {
            int r = i / 48, cc = 128 + (i % 48);
            int m = m0 + r;
            float v = (cc < 163 && m < N_ATOMS)
                      ? __ldcs(&fatoms[(size_t)m * AF + (cc - 128)]) : 0.f;
            unsigned short h, l;
            split2(v, h, l);
            Ahi[r * ASTRA + cc] = __ushort_as_bfloat16(h);
            Alo[r * ASTRA + cc] = __ushort_as_bfloat16(l);
        }
        __syncthreads();

        int r0 = (warp & 3) * 16 + g;
        int tbase = (warp >> 2) * 8;
        float c[8][4];
#pragma unroll
        for (int t = 0; t < 8; t++)
#pragma unroll
            for (int j = 0; j < 4; j++) c[t][j] = 0.f;

#pragma unroll
        for (int s = 0; s < NS_A; s++) {
            int k0 = s * 16 + tig * 2;
            uint32_t ah0 = *(const uint32_t*)&Ahi[(r0    ) * ASTRA + k0];
            uint32_t ah1 = *(const uint32_t*)&Ahi[(r0 + 8) * ASTRA + k0];
            uint32_t ah2 = *(const uint32_t*)&Ahi[(r0    ) * ASTRA + k0 + 8];
            uint32_t ah3 = *(const uint32_t*)&Ahi[(r0 + 8) * ASTRA + k0 + 8];
            uint32_t al0 = *(const uint32_t*)&Alo[(r0    ) * ASTRA + k0];
            uint32_t al1 = *(const uint32_t*)&Alo[(r0 + 8) * ASTRA + k0];
            uint32_t al2 = *(const uint32_t*)&Alo[(r0    ) * ASTRA + k0 + 8];
            uint32_t al3 = *(const uint32_t*)&Alo[(r0 + 8) * ASTRA + k0 + 8];
#pragma unroll
            for (int t = 0; t < 8; t++) {
                int fi = s * 512 + (tbase + t) * 32 + lane;
                uint2 bh = WH[fi];
                uint2 bl = __ldg(&g_wfo_lo[fi]);
                MMA16816(c[t], ah0, ah1, ah2, ah3, bh.x, bh.y);
                MMA16816(c[t], ah0, ah1, ah2, ah3, bl.x, bl.y);
                MMA16816(c[t], al0, al1, al2, al3, bh.x, bh.y);
            }
        }

        int mA = m0 + r0;
        int mB = mA + 8;
        int ncol0 = (warp >> 2) * 64 + tig * 2;
#pragma unroll
        for (int t = 0; t < 8; t++) {
            int n0 = ncol0 + t * 8;
            float2 bo = *(const float2*)&b_o[n0];
            if (mA < N_ATOMS) {
                float2 o = make_float2(fmaxf(bo.x + c[t][0], 0.f),
                                       fmaxf(bo.y + c[t][1], 0.f));
                __stcs((float2*)&g_atomh[(size_t)mA * H + n0], o);
            }
            if (mB < N_ATOMS) {
                float2 o = make_float2(fmaxf(bo.x + c[t][2], 0.f),
                                       fmaxf(bo.y + c[t][3], 0.f));
                __stcs((float2*)&g_atomh[(size_t)mB * H + n0], o);
            }
        }
    }
}

// ---------------------------------------------------------------
__device__ __forceinline__ int lowerb(const int* __restrict__ a, int n, int key) {
    int lo = 0, hi = n;
    while (lo < hi) {
        int mid = (lo + hi) >> 1;
        if (a[mid] < key) lo = mid + 1; else hi = mid;
    }
    return lo;
}

__global__ void pool_kernel(const int* __restrict__ mol_ids,
                            float* __restrict__ out) {
    int mol = blockIdx.x;
    int tid = threadIdx.x;
    int lo = lowerb(mol_ids, N_ATOMS, mol);
    int hi = lowerb(mol_ids, N_ATOMS, mol + 1);
    float s = 0.f;
    for (int a = lo; a < hi; a++)
        s += __ldcs(&g_atomh[(size_t)a * H + tid]);
    int cnt = hi - lo;
    out[(size_t)mol * H + tid] = cnt ? s / (float)cnt : 0.f;
}

// ---------------------------------------------------------------
extern "C" void kernel_launch(void* const* d_in, const int* in_sizes, int n_in,
                              void* d_out, int out_size) {
    const float *fatoms = nullptr, *fbonds = nullptr, *tree = nullptr;
    const float *W_i = nullptr, *W_h = nullptr, *W_o = nullptr, *b_o = nullptr;
    const int *agraph = nullptr, *bgraph = nullptr, *mol_ids = nullptr;
    for (int i = 0; i < n_in; i++) {
        switch (in_sizes[i]) {
            case 3500000: fatoms  = (const float*)d_in[i]; break;   // 100000*35
            case 8800000: fbonds  = (const float*)d_in[i]; break;   // 220000*40
            case 2560000: tree    = (const float*)d_in[i]; break;   // 20000*128
            case 1000000: agraph  = (const int*)d_in[i];   break;   // 100000*10
            case 2200000: bgraph  = (const int*)d_in[i];   break;   // 220000*10
            case 100000:  mol_ids = (const int*)d_in[i];   break;
            case 5120:    W_i     = (const float*)d_in[i]; break;   // 40*128
            case 16384:   W_h     = (const float*)d_in[i]; break;   // 128*128
            case 20864:   W_o     = (const float*)d_in[i]; break;   // 163*128
            case 128:     b_o     = (const float*)d_in[i]; break;
        }
    }

    const int BIN_SMEM  = (TM * BF + BF * H) * 4;
    const int BOND_SMEM = BMT * ASTR * 2 * 2 + 4096 * 8 * 2;   // 100352
    const int ATOM_SMEM = 64 * ASTRA * 2 * 2 + NS_A * 512 * 8; // 92160
    cudaFuncSetAttribute(bond_mma_kernel,
                         cudaFuncAttributeMaxDynamicSharedMemorySize, BOND_SMEM);
    cudaFuncSetAttribute(atom_mma_kernel,
                         cudaFuncAttributeMaxDynamicSharedMemorySize, ATOM_SMEM);

    float *msgA, *msgB;
    cudaGetSymbolAddress((void**)&msgA, g_msgA);
    cudaGetSymbolAddress((void**)&msgB, g_msgB);

    int tc_blocks = (N_MESS * H / 4 + 255) / 256;
    tree_copy_kernel<<<tc_blocks, 256>>>(tree);
    prep_w_kernel<<<(8 * 16 * 32 + 255) / 256, 256>>>(W_h);
    prep_wo_kernel<<<(NS_A * 16 * 32 + 255) / 256, 256>>>(W_o);

    int grid_bin = (N_BONDS + TM - 1) / TM;
    binput_kernel<<<grid_bin, TB, BIN_SMEM>>>(fbonds, W_i);

    float* src = msgA;
    float* dst = msgB;
    for (int it = 0; it < 5; it++) {            // DEPTH-1
        bond_mma_kernel<<<PGRID, 256, BOND_SMEM>>>(
            src, dst + (size_t)N_MESS * H, bgraph);
        float* t = src; src = dst; dst = t;
    }

    atom_mma_kernel<<<PGRID, 256, ATOM_SMEM>>>(src, agraph, fatoms, b_o);

    pool_kernel<<<N_MOLS, H>>>(mol_ids, (float*)d_out);
}

// round 10
// speedup vs baseline: 1.1811x; 1.1811x over previous
#include <cuda_runtime.h>
#include <cuda_bf16.h>
#include <cstdint>

#define H       128
#define NBR     10
#define AF      35
#define BF      40            // ATOM_FDIM + BOND_FDIM
#define N_ATOMS 100000
#define N_BONDS 220000
#define N_MESS  20000
#define N_MOLS  2000
#define MSG_ROWS (N_MESS + N_BONDS)
#define TM      64            // rows per block tile (SIMT binput)
#define TB      256

// bond mma kernel tiling
#define BMT     64            // rows per block
#define ASTR    136           // A row stride (bf16), conflict-free fragments
// atom mma kernel tiling
#define ASTRA   184           // A row stride (bf16), conflict-free fragments
#define NS_A    11            // k-steps for atom

// ---- scratch (device globals: allocation-free kernel_launch) ----
__device__ float g_msgA[(size_t)MSG_ROWS * H];
__device__ float g_msgB[(size_t)MSG_ROWS * H];
__device__ float g_binput[(size_t)N_BONDS * H];
__device__ float g_atomh[(size_t)N_ATOMS * H];
// W_h fragments: [kstep 8][ntile 16][lane 32] uint2, hi & lo planes
__device__ uint2 g_wf_hi[8 * 16 * 32];
__device__ uint2 g_wf_lo[8 * 16 * 32];
// W_o (reordered+padded) fragments: [kstep 11][ntile 16][lane 32]
__device__ uint2 g_wfo_hi[NS_A * 16 * 32];
__device__ uint2 g_wfo_lo[NS_A * 16 * 32];

#define MMA16816(c, a0, a1, a2, a3, b0, b1) \
    asm volatile("mma.sync.aligned.m16n8k16.row.col.f32.bf16.bf16.f32 " \
        "{%0,%1,%2,%3}, {%4,%5,%6,%7}, {%8,%9}, {%0,%1,%2,%3};" \
        : "+f"((c)[0]), "+f"((c)[1]), "+f"((c)[2]), "+f"((c)[3]) \
        : "r"(a0), "r"(a1), "r"(a2), "r"(a3), "r"(b0), "r"(b1))

__device__ __forceinline__ unsigned short bf16hi(float v) {
    return __bfloat16_as_ushort(__float2bfloat16_rn(v));
}
__device__ __forceinline__ void split2(float v, unsigned short& h, unsigned short& l) {
    h = bf16hi(v);
    l = bf16hi(v - __bfloat162float(__ushort_as_bfloat16(h)));
}

// ---------------------------------------------------------------
__global__ void tree_copy_kernel(const float* __restrict__ tree) {
    int i = blockIdx.x * blockDim.x + threadIdx.x;
    int n4 = N_MESS * H / 4;
    if (i < n4) {
        float4 v = ((const float4*)tree)[i];
        ((float4*)g_msgA)[i] = v;
        ((float4*)g_msgB)[i] = v;
    }
}

// ---------------------------------------------------------------
// W_h [k][n] -> bf16 hi/lo B-fragments (m16n8k16):
// i = s*512 + t*32 + lane; g=lane>>2, tig=lane&3; n=t*8+g; k0=s*16+tig*2
__global__ void prep_w_kernel(const float* __restrict__ W_h) {
    int i = blockIdx.x * blockDim.x + threadIdx.x;
    if (i >= 8 * 16 * 32) return;
    int lane = i & 31, t = (i >> 5) & 15, s = i >> 9;
    int g = lane >> 2, tig = lane & 3;
    int n = t * 8 + g;
    int k0 = s * 16 + tig * 2;
    float w[4] = { W_h[(k0 + 0) * H + n], W_h[(k0 + 1) * H + n],
                   W_h[(k0 + 8) * H + n], W_h[(k0 + 9) * H + n] };
    unsigned short h[4], l[4];
#pragma unroll
    for (int j = 0; j < 4; j++) split2(w[j], h[j], l[j]);
    g_wf_hi[i] = make_uint2((uint32_t)h[0] | ((uint32_t)h[1] << 16),
                            (uint32_t)h[2] | ((uint32_t)h[3] << 16));
    g_wf_lo[i] = make_uint2((uint32_t)l[0] | ((uint32_t)l[1] << 16),
                            (uint32_t)l[2] | ((uint32_t)l[3] << 16));
}

// W_o reordered (A col k: k<128 -> W_o row 35+k; 128..162 -> row k-128; else 0)
__device__ __forceinline__ float wo_val(const float* W_o, int k, int n) {
    if (k < 128)  return W_o[(size_t)(35 + k) * H + n];
    if (k < 163)  return W_o[(size_t)(k - 128) * H + n];
    return 0.f;
}
__global__ void prep_wo_kernel(const float* __restrict__ W_o) {
    int i = blockIdx.x * blockDim.x + threadIdx.x;
    if (i >= NS_A * 16 * 32) return;
    int lane = i & 31, t = (i >> 5) & 15, s = i >> 9;
    int g = lane >> 2, tig = lane & 3;
    int n = t * 8 + g;
    int k0 = s * 16 + tig * 2;
    float w[4] = { wo_val(W_o, k0 + 0, n), wo_val(W_o, k0 + 1, n),
                   wo_val(W_o, k0 + 8, n), wo_val(W_o, k0 + 9, n) };
    unsigned short h[4], l[4];
#pragma unroll
    for (int j = 0; j < 4; j++) split2(w[j], h[j], l[j]);
    g_wfo_hi[i] = make_uint2((uint32_t)h[0] | ((uint32_t)h[1] << 16),
                             (uint32_t)h[2] | ((uint32_t)h[3] << 16));
    g_wfo_lo[i] = make_uint2((uint32_t)l[0] | ((uint32_t)l[1] << 16),
                             (uint32_t)l[2] | ((uint32_t)l[3] << 16));
}

// ---------------------------------------------------------------
// binput = fbonds @ W_i ; msgA graph part = relu(binput)   (SIMT)
__global__ void binput_kernel(const float* __restrict__ fbonds,
                              const float* __restrict__ W_i) {
    extern __shared__ float sm[];
    float* Asm = sm;             // [TM][BF]
    float* Wsm = sm + TM * BF;   // [BF][H]
    int m0 = blockIdx.x * TM;
    int tid = threadIdx.x;
    int warp = tid >> 5, lane = tid & 31;

    for (int i = tid * 4; i < BF * H; i += TB * 4)
        *(float4*)&Wsm[i] = *(const float4*)&W_i[i];
    for (int i = tid; i < TM * BF; i += TB) {
        int r = i / BF, c = i % BF;
        int m = m0 + r;
        Asm[i] = (m < N_BONDS) ? fbonds[(size_t)m * BF + c] : 0.f;
    }
    __syncthreads();

    float acc[8][4];
#pragma unroll
    for (int i = 0; i < 8; i++)
#pragma unroll
        for (int j = 0; j < 4; j++) acc[i][j] = 0.f;
    int n0 = lane * 4;
#pragma unroll
    for (int kk = 0; kk < BF; kk += 4) {
        float4 b0 = *(float4*)&Wsm[(kk + 0) * H + n0];
        float4 b1 = *(float4*)&Wsm[(kk + 1) * H + n0];
        float4 b2 = *(float4*)&Wsm[(kk + 2) * H + n0];
        float4 b3 = *(float4*)&Wsm[(kk + 3) * H + n0];
#pragma unroll
        for (int i = 0; i < 8; i++) {
            float4 a = *(float4*)&Asm[(warp * 8 + i) * BF + kk];
            acc[i][0] += a.x * b0.x + a.y * b1.x + a.z * b2.x + a.w * b3.x;
            acc[i][1] += a.x * b0.y + a.y * b1.y + a.z * b2.y + a.w * b3.y;
            acc[i][2] += a.x * b0.z + a.y * b1.z + a.z * b2.z + a.w * b3.z;
            acc[i][3] += a.x * b0.w + a.y * b1.w + a.z * b2.w + a.w * b3.w;
        }
    }
    float* graphA = g_msgA + (size_t)N_MESS * H;
#pragma unroll
    for (int i = 0; i < 8; i++) {
        int m = m0 + warp * 8 + i;
        if (m < N_BONDS) {
            float4 v = make_float4(acc[i][0], acc[i][1], acc[i][2], acc[i][3]);
            *(float4*)&g_binput[(size_t)m * H + n0] = v;
            float4 r = make_float4(fmaxf(v.x, 0.f), fmaxf(v.y, 0.f),
                                   fmaxf(v.z, 0.f), fmaxf(v.w, 0.f));
            *(float4*)&graphA[(size_t)m * H + n0] = r;
        }
    }
}

// ---------------------------------------------------------------
// bond iter: dst = relu(binput + gathersum(src)@W_h)
// 512 threads / 16 warps; warp tile 16 rows x 32 cols (c[4][4] = 16 accum
// regs) so regs/thread <= 64 -> 1024 threads/SM = 50% occupancy (2x R7).
// Occupancy is register-limited; this is the latency-hiding lever for the
// random 10-neighbor gather.
__global__ void __launch_bounds__(512, 2)
bond_mma_kernel(const float* __restrict__ src_msg,
                float* __restrict__ dst_graph,
                const int* __restrict__ bgraph) {
    extern __shared__ char smem[];
    __nv_bfloat16* Ahi = (__nv_bfloat16*)smem;            // [BMT][ASTR]
    __nv_bfloat16* Alo = Ahi + BMT * ASTR;
    uint2* WH = (uint2*)(Alo + BMT * ASTR);               // [4096]
    uint2* WL = WH + 4096;

    int tid = threadIdx.x, warp = tid >> 5, lane = tid & 31;
    int m0 = blockIdx.x * BMT;

    // stage W fragments (64 KB = 2 x 2048 uint4)
    {
        const uint4* sh = (const uint4*)g_wf_hi;
        const uint4* sl = (const uint4*)g_wf_lo;
        uint4* dh = (uint4*)WH;
        uint4* dl = (uint4*)WL;
        for (int i = tid; i < 2048; i += 512) { dh[i] = sh[i]; dl[i] = sl[i]; }
    }

    // gather: warp -> 4 rows, lane -> cols [4l, 4l+4)
#pragma unroll
    for (int i = 0; i < 4; i++) {
        int r = warp * 4 + i;
        int m = m0 + r;
        float4 acc = make_float4(0.f, 0.f, 0.f, 0.f);
        if (m < N_BONDS) {
            const int* bg = &bgraph[m * NBR];
#pragma unroll
            for (int nb = 0; nb < NBR; nb++) {
                int idx = __ldg(&bg[nb]);
                float4 v = *(const float4*)&src_msg[(size_t)idx * H + lane * 4];
                acc.x += v.x; acc.y += v.y; acc.z += v.z; acc.w += v.w;
            }
        }
        float a[4] = {acc.x, acc.y, acc.z, acc.w};
        unsigned short hs[4], ls[4];
#pragma unroll
        for (int j = 0; j < 4; j++) split2(a[j], hs[j], ls[j]);
        *(uint2*)&Ahi[r * ASTR + lane * 4] =
            make_uint2((uint32_t)hs[0] | ((uint32_t)hs[1] << 16),
                       (uint32_t)hs[2] | ((uint32_t)hs[3] << 16));
        *(uint2*)&Alo[r * ASTR + lane * 4] =
            make_uint2((uint32_t)ls[0] | ((uint32_t)ls[1] << 16),
                       (uint32_t)ls[2] | ((uint32_t)ls[3] << 16));
    }
    __syncthreads();

    // MMA: warp (w&3) -> 16-row group, (w>>2) -> 32-col group
    int g = lane >> 2, tig = lane & 3;
    int r0 = (warp & 3) * 16 + g;
    int tbase = (warp >> 2) * 4;
    float c[4][4];
#pragma unroll
    for (int t = 0; t < 4; t++)
#pragma unroll
        for (int j = 0; j < 4; j++) c[t][j] = 0.f;

#pragma unroll
    for (int s = 0; s < 8; s++) {
        int k0 = s * 16 + tig * 2;
        uint32_t ah0 = *(const uint32_t*)&Ahi[(r0    ) * ASTR + k0];
        uint32_t ah1 = *(const uint32_t*)&Ahi[(r0 + 8) * ASTR + k0];
        uint32_t ah2 = *(const uint32_t*)&Ahi[(r0    ) * ASTR + k0 + 8];
        uint32_t ah3 = *(const uint32_t*)&Ahi[(r0 + 8) * ASTR + k0 + 8];
        uint32_t al0 = *(const uint32_t*)&Alo[(r0    ) * ASTR + k0];
        uint32_t al1 = *(const uint32_t*)&Alo[(r0 + 8) * ASTR + k0];
        uint32_t al2 = *(const uint32_t*)&Alo[(r0    ) * ASTR + k0 + 8];
        uint32_t al3 = *(const uint32_t*)&Alo[(r0 + 8) * ASTR + k0 + 8];
#pragma unroll
        for (int t = 0; t < 4; t++) {
            uint2 bh = WH[s * 512 + (tbase + t) * 32 + lane];
            uint2 bl = WL[s * 512 + (tbase + t) * 32 + lane];
            MMA16816(c[t], ah0, ah1, ah2, ah3, bh.x, bh.y);
            MMA16816(c[t], ah0, ah1, ah2, ah3, bl.x, bl.y);
            MMA16816(c[t], al0, al1, al2, al3, bh.x, bh.y);
        }
    }

    // epilogue
    int mA = m0 + r0;
    int mB = mA + 8;
    int ncol0 = (warp >> 2) * 32 + tig * 2;
#pragma unroll
    for (int t = 0; t < 4; t++) {
        int n0 = ncol0 + t * 8;
        if (mA < N_BONDS) {
            float2 bi = *(const float2*)&g_binput[(size_t)mA * H + n0];
            float2 o = make_float2(fmaxf(bi.x + c[t][0], 0.f),
                                   fmaxf(bi.y + c[t][1], 0.f));
            *(float2*)&dst_graph[(size_t)mA * H + n0] = o;
        }
        if (mB < N_BONDS) {
            float2 bi = *(const float2*)&g_binput[(size_t)mB * H + n0];
            float2 o = make_float2(fmaxf(bi.x + c[t][2], 0.f),
                                   fmaxf(bi.y + c[t][3], 0.f));
            *(float2*)&dst_graph[(size_t)mB * H + n0] = o;
        }
    }
}

// ---------------------------------------------------------------
// atom: g_atomh = relu([nei(128)|fatoms(35)|pad] @ Wo_frag + b_o)  via mma
// (unchanged from the 1645us R7 version)
__global__ void __launch_bounds__(256, 2)
atom_mma_kernel(const float* __restrict__ src_msg,
                const int* __restrict__ agraph,
                const float* __restrict__ fatoms,
                const float* __restrict__ b_o) {
    extern __shared__ char smem[];
    __nv_bfloat16* Ahi = (__nv_bfloat16*)smem;            // [64][ASTRA]
    __nv_bfloat16* Alo = Ahi + 64 * ASTRA;
    uint2* WH = (uint2*)(Alo + 64 * ASTRA);               // [NS_A*512]

    int tid = threadIdx.x, warp = tid >> 5, lane = tid & 31;
    int m0 = blockIdx.x * 64;

    // stage Wo hi fragments: NS_A*512 uint2 = 45056 B = 2816 uint4
    {
        const uint4* sh = (const uint4*)g_wfo_hi;
        uint4* dh = (uint4*)WH;
        for (int i = tid; i < 2816; i += 256) dh[i] = sh[i];
    }

    // nei gather into cols [0,128)
#pragma unroll
    for (int i = 0; i < 8; i++) {
        int r = warp * 8 + i;
        int m = m0 + r;
        float4 acc = make_float4(0.f, 0.f, 0.f, 0.f);
        if (m < N_ATOMS) {
            const int* ag = &agraph[m * NBR];
#pragma unroll
            for (int nb = 0; nb < NBR; nb++) {
                int idx = __ldg(&ag[nb]);
                float4 v = *(const float4*)&src_msg[(size_t)idx * H + lane * 4];
                acc.x += v.x; acc.y += v.y; acc.z += v.z; acc.w += v.w;
            }
        }
        float a[4] = {acc.x, acc.y, acc.z, acc.w};
        unsigned short hs[4], ls[4];
#pragma unroll
        for (int j = 0; j < 4; j++) split2(a[j], hs[j], ls[j]);
        *(uint2*)&Ahi[r * ASTRA + lane * 4] =
            make_uint2((uint32_t)hs[0] | ((uint32_t)hs[1] << 16),
                       (uint32_t)hs[2] | ((uint32_t)hs[3] << 16));
        *(uint2*)&Alo[r * ASTRA + lane * 4] =
            make_uint2((uint32_t)ls[0] | ((uint32_t)ls[1] << 16),
                       (uint32_t)ls[2] | ((uint32_t)ls[3] << 16));
    }
    // fatoms into cols [128,163), zero pad [163,176)
    for (int i = tid; i < 64 * 48; i += 256) {
        int r = i / 48, cc = 128 + (i % 48);
        int m = m0 + r;
        float v = (cc < 163 && m < N_ATOMS)
                  ? fatoms[(size_t)m * AF + (cc - 128)] : 0.f;
        unsigned short h, l;
        split2(v, h, l);
        Ahi[r * ASTRA + cc] = __ushort_as_bfloat16(h);
        Alo[r * ASTRA + cc] = __ushort_as_bfloat16(l);
    }
    __syncthreads();

    int g = lane >> 2, tig = lane & 3;
    int r0 = (warp & 3) * 16 + g;
    int tbase = (warp >> 2) * 8;
    float c[8][4];
#pragma unroll
    for (int t = 0; t < 8; t++)
#pragma unroll
        for (int j = 0; j < 4; j++) c[t][j] = 0.f;

#pragma unroll
    for (int s = 0; s < NS_A; s++) {
        int k0 = s * 16 + tig * 2;
        uint32_t ah0 = *(const uint32_t*)&Ahi[(r0    ) * ASTRA + k0];
        uint32_t ah1 = *(const uint32_t*)&Ahi[(r0 + 8) * ASTRA + k0];
        uint32_t ah2 = *(const uint32_t*)&Ahi[(r0    ) * ASTRA + k0 + 8];
        uint32_t ah3 = *(const uint32_t*)&Ahi[(r0 + 8) * ASTRA + k0 + 8];
        uint32_t al0 = *(const uint32_t*)&Alo[(r0    ) * ASTRA + k0];
        uint32_t al1 = *(const uint32_t*)&Alo[(r0 + 8) * ASTRA + k0];
        uint32_t al2 = *(const uint32_t*)&Alo[(r0    ) * ASTRA + k0 + 8];
        uint32_t al3 = *(const uint32_t*)&Alo[(r0 + 8) * ASTRA + k0 + 8];
#pragma unroll
        for (int t = 0; t < 8; t++) {
            int fi = s * 512 + (tbase + t) * 32 + lane;
            uint2 bh = WH[fi];
            uint2 bl = __ldg(&g_wfo_lo[fi]);
            MMA16816(c[t], ah0, ah1, ah2, ah3, bh.x, bh.y);
            MMA16816(c[t], ah0, ah1, ah2, ah3, bl.x, bl.y);
            MMA16816(c[t], al0, al1, al2, al3, bh.x, bh.y);
        }
    }

    int mA = m0 + r0;
    int mB = mA + 8;
    int ncol0 = (warp >> 2) * 64 + tig * 2;
#pragma unroll
    for (int t = 0; t < 8; t++) {
        int n0 = ncol0 + t * 8;
        float2 bo = *(const float2*)&b_o[n0];
        if (mA < N_ATOMS) {
            float2 o = make_float2(fmaxf(bo.x + c[t][0], 0.f),
                                   fmaxf(bo.y + c[t][1], 0.f));
            *(float2*)&g_atomh[(size_t)mA * H + n0] = o;
        }
        if (mB < N_ATOMS) {
            float2 o = make_float2(fmaxf(bo.x + c[t][2], 0.f),
                                   fmaxf(bo.y + c[t][3], 0.f));
            *(float2*)&g_atomh[(size_t)mB * H + n0] = o;
        }
    }
}

// ---------------------------------------------------------------
__device__ __forceinline__ int lowerb(const int* __restrict__ a, int n, int key) {
    int lo = 0, hi = n;
    while (lo < hi) {
        int mid = (lo + hi) >> 1;
        if (a[mid] < key) lo = mid + 1; else hi = mid;
    }
    return lo;
}

__global__ void pool_kernel(const int* __restrict__ mol_ids,
                            float* __restrict__ out) {
    int mol = blockIdx.x;
    int tid = threadIdx.x;
    int lo = lowerb(mol_ids, N_ATOMS, mol);
    int hi = lowerb(mol_ids, N_ATOMS, mol + 1);
    float s = 0.f;
    for (int a = lo; a < hi; a++)
        s += g_atomh[(size_t)a * H + tid];
    int cnt = hi - lo;
    out[(size_t)mol * H + tid] = cnt ? s / (float)cnt : 0.f;
}

// ---------------------------------------------------------------
extern "C" void kernel_launch(void* const* d_in, const int* in_sizes, int n_in,
                              void* d_out, int out_size) {
    const float *fatoms = nullptr, *fbonds = nullptr, *tree = nullptr;
    const float *W_i = nullptr, *W_h = nullptr, *W_o = nullptr, *b_o = nullptr;
    const int *agraph = nullptr, *bgraph = nullptr, *mol_ids = nullptr;
    for (int i = 0; i < n_in; i++) {
        switch (in_sizes[i]) {
            case 3500000: fatoms  = (const float*)d_in[i]; break;   // 100000*35
            case 8800000: fbonds  = (const float*)d_in[i]; break;   // 220000*40
            case 2560000: tree    = (const float*)d_in[i]; break;   // 20000*128
            case 1000000: agraph  = (const int*)d_in[i];   break;   // 100000*10
            case 2200000: bgraph  = (const int*)d_in[i];   break;   // 220000*10
            case 100000:  mol_ids = (const int*)d_in[i];   break;
            case 5120:    W_i     = (const float*)d_in[i]; break;   // 40*128
            case 16384:   W_h     = (const float*)d_in[i]; break;   // 128*128
            case 20864:   W_o     = (const float*)d_in[i]; break;   // 163*128
            case 128:     b_o     = (const float*)d_in[i]; break;
        }
    }

    const int BIN_SMEM  = (TM * BF + BF * H) * 4;
    const int BOND_SMEM = BMT * ASTR * 2 * 2 + 4096 * 8 * 2;   // 100352
    const int ATOM_SMEM = 64 * ASTRA * 2 * 2 + NS_A * 512 * 8; // 92160
    cudaFuncSetAttribute(bond_mma_kernel,
                         cudaFuncAttributeMaxDynamicSharedMemorySize, BOND_SMEM);
    cudaFuncSetAttribute(atom_mma_kernel,
                         cudaFuncAttributeMaxDynamicSharedMemorySize, ATOM_SMEM);

    float *msgA, *msgB;
    cudaGetSymbolAddress((void**)&msgA, g_msgA);
    cudaGetSymbolAddress((void**)&msgB, g_msgB);

    int tc_blocks = (N_MESS * H / 4 + 255) / 256;
    tree_copy_kernel<<<tc_blocks, 256>>>(tree);
    prep_w_kernel<<<(8 * 16 * 32 + 255) / 256, 256>>>(W_h);
    prep_wo_kernel<<<(NS_A * 16 * 32 + 255) / 256, 256>>>(W_o);

    int grid_bin = (N_BONDS + TM - 1) / TM;
    binput_kernel<<<grid_bin, TB, BIN_SMEM>>>(fbonds, W_i);

    float* src = msgA;
    float* dst = msgB;
    int grid_mma = (N_BONDS + BMT - 1) / BMT;   // 3438
    for (int it = 0; it < 5; it++) {            // DEPTH-1
        bond_mma_kernel<<<grid_mma, 512, BOND_SMEM>>>(
            src, dst + (size_t)N_MESS * H, bgraph);
        float* t = src; src = dst; dst = t;
    }

    int grid_a = (N_ATOMS + 63) / 64;           // 1563
    atom_mma_kernel<<<grid_a, 256, ATOM_SMEM>>>(src, agraph, fatoms, b_o);

    pool_kernel<<<N_MOLS, H>>>(mol_ids, (float*)d_out);
}

// round 11
// speedup vs baseline: 1.6941x; 1.4343x over previous
#include <cuda_runtime.h>
#include <cuda_bf16.h>
#include <cuda_fp16.h>
#include <cstdint>

#define H       128
#define NBR     10
#define AF      35
#define BF      40            // ATOM_FDIM + BOND_FDIM
#define N_ATOMS 100000
#define N_BONDS 220000
#define N_MESS  20000
#define N_MOLS  2000
#define MSG_ROWS (N_MESS + N_BONDS)
#define TM      64            // rows per block tile (SIMT binput)
#define TB      256

// bond mma kernel tiling
#define BMT     64            // rows per block
#define ASTR    136           // A row stride (bf16), conflict-free fragments
// atom mma kernel tiling
#define ASTRA   184           // A row stride (bf16), conflict-free fragments
#define NS_A    11            // k-steps for atom

// ---- scratch (device globals: allocation-free kernel_launch) ----
// messages stored fp16: halves gather/store traffic; 5e-4 quantization,
// summed in fp32 and hi/lo-split for the MMA so GEMM precision unchanged.
__device__ __half g_msgA[(size_t)MSG_ROWS * H];
__device__ __half g_msgB[(size_t)MSG_ROWS * H];
__device__ float g_binput[(size_t)N_BONDS * H];
__device__ float g_atomh[(size_t)N_ATOMS * H];
// W_h fragments: [kstep 8][ntile 16][lane 32] uint2, hi & lo planes
__device__ uint2 g_wf_hi[8 * 16 * 32];
__device__ uint2 g_wf_lo[8 * 16 * 32];
// W_o (reordered+padded) fragments: [kstep 11][ntile 16][lane 32]
__device__ uint2 g_wfo_hi[NS_A * 16 * 32];
__device__ uint2 g_wfo_lo[NS_A * 16 * 32];

#define MMA16816(c, a0, a1, a2, a3, b0, b1) \
    asm volatile("mma.sync.aligned.m16n8k16.row.col.f32.bf16.bf16.f32 " \
        "{%0,%1,%2,%3}, {%4,%5,%6,%7}, {%8,%9}, {%0,%1,%2,%3};" \
        : "+f"((c)[0]), "+f"((c)[1]), "+f"((c)[2]), "+f"((c)[3]) \
        : "r"(a0), "r"(a1), "r"(a2), "r"(a3), "r"(b0), "r"(b1))

__device__ __forceinline__ unsigned short bf16hi(float v) {
    return __bfloat16_as_ushort(__float2bfloat16_rn(v));
}
__device__ __forceinline__ void split2(float v, unsigned short& h, unsigned short& l) {
    h = bf16hi(v);
    l = bf16hi(v - __bfloat162float(__ushort_as_bfloat16(h)));
}
// accumulate 4 fp16 (as uint2) into float4
__device__ __forceinline__ void acc4h(float4& acc, uint2 v) {
    float2 f0 = __half22float2(*reinterpret_cast<__half2*>(&v.x));
    float2 f1 = __half22float2(*reinterpret_cast<__half2*>(&v.y));
    acc.x += f0.x; acc.y += f0.y; acc.z += f1.x; acc.w += f1.y;
}

// ---------------------------------------------------------------
__global__ void tree_copy_kernel(const float* __restrict__ tree) {
    int i = blockIdx.x * blockDim.x + threadIdx.x;
    int n4 = N_MESS * H / 4;
    if (i < n4) {
        float4 v = ((const float4*)tree)[i];
        __half2 h0 = __float22half2_rn(make_float2(v.x, v.y));
        __half2 h1 = __float22half2_rn(make_float2(v.z, v.w));
        uint2 p = make_uint2(*reinterpret_cast<uint32_t*>(&h0),
                             *reinterpret_cast<uint32_t*>(&h1));
        ((uint2*)g_msgA)[i] = p;
        ((uint2*)g_msgB)[i] = p;
    }
}

// ---------------------------------------------------------------
// W_h [k][n] -> bf16 hi/lo B-fragments (m16n8k16):
// i = s*512 + t*32 + lane; g=lane>>2, tig=lane&3; n=t*8+g; k0=s*16+tig*2
__global__ void prep_w_kernel(const float* __restrict__ W_h) {
    int i = blockIdx.x * blockDim.x + threadIdx.x;
    if (i >= 8 * 16 * 32) return;
    int lane = i & 31, t = (i >> 5) & 15, s = i >> 9;
    int g = lane >> 2, tig = lane & 3;
    int n = t * 8 + g;
    int k0 = s * 16 + tig * 2;
    float w[4] = { W_h[(k0 + 0) * H + n], W_h[(k0 + 1) * H + n],
                   W_h[(k0 + 8) * H + n], W_h[(k0 + 9) * H + n] };
    unsigned short h[4], l[4];
#pragma unroll
    for (int j = 0; j < 4; j++) split2(w[j], h[j], l[j]);
    g_wf_hi[i] = make_uint2((uint32_t)h[0] | ((uint32_t)h[1] << 16),
                            (uint32_t)h[2] | ((uint32_t)h[3] << 16));
    g_wf_lo[i] = make_uint2((uint32_t)l[0] | ((uint32_t)l[1] << 16),
                            (uint32_t)l[2] | ((uint32_t)l[3] << 16));
}

// W_o reordered (A col k: k<128 -> W_o row 35+k; 128..162 -> row k-128; else 0)
__device__ __forceinline__ float wo_val(const float* W_o, int k, int n) {
    if (k < 128)  return W_o[(size_t)(35 + k) * H + n];
    if (k < 163)  return W_o[(size_t)(k - 128) * H + n];
    return 0.f;
}
__global__ void prep_wo_kernel(const float* __restrict__ W_o) {
    int i = blockIdx.x * blockDim.x + threadIdx.x;
    if (i >= NS_A * 16 * 32) return;
    int lane = i & 31, t = (i >> 5) & 15, s = i >> 9;
    int g = lane >> 2, tig = lane & 3;
    int n = t * 8 + g;
    int k0 = s * 16 + tig * 2;
    float w[4] = { wo_val(W_o, k0 + 0, n), wo_val(W_o, k0 + 1, n),
                   wo_val(W_o, k0 + 8, n), wo_val(W_o, k0 + 9, n) };
    unsigned short h[4], l[4];
#pragma unroll
    for (int j = 0; j < 4; j++) split2(w[j], h[j], l[j]);
    g_wfo_hi[i] = make_uint2((uint32_t)h[0] | ((uint32_t)h[1] << 16),
                             (uint32_t)h[2] | ((uint32_t)h[3] << 16));
    g_wfo_lo[i] = make_uint2((uint32_t)l[0] | ((uint32_t)l[1] << 16),
                             (uint32_t)l[2] | ((uint32_t)l[3] << 16));
}

// ---------------------------------------------------------------
// binput = fbonds @ W_i ; msgA graph part = relu(binput) as fp16   (SIMT)
__global__ void binput_kernel(const float* __restrict__ fbonds,
                              const float* __restrict__ W_i) {
    extern __shared__ float sm[];
    float* Asm = sm;             // [TM][BF]
    float* Wsm = sm + TM * BF;   // [BF][H]
    int m0 = blockIdx.x * TM;
    int tid = threadIdx.x;
    int warp = tid >> 5, lane = tid & 31;

    for (int i = tid * 4; i < BF * H; i += TB * 4)
        *(float4*)&Wsm[i] = *(const float4*)&W_i[i];
    for (int i = tid; i < TM * BF; i += TB) {
        int r = i / BF, c = i % BF;
        int m = m0 + r;
        Asm[i] = (m < N_BONDS) ? fbonds[(size_t)m * BF + c] : 0.f;
    }
    __syncthreads();

    float acc[8][4];
#pragma unroll
    for (int i = 0; i < 8; i++)
#pragma unroll
        for (int j = 0; j < 4; j++) acc[i][j] = 0.f;
    int n0 = lane * 4;
#pragma unroll
    for (int kk = 0; kk < BF; kk += 4) {
        float4 b0 = *(float4*)&Wsm[(kk + 0) * H + n0];
        float4 b1 = *(float4*)&Wsm[(kk + 1) * H + n0];
        float4 b2 = *(float4*)&Wsm[(kk + 2) * H + n0];
        float4 b3 = *(float4*)&Wsm[(kk + 3) * H + n0];
#pragma unroll
        for (int i = 0; i < 8; i++) {
            float4 a = *(float4*)&Asm[(warp * 8 + i) * BF + kk];
            acc[i][0] += a.x * b0.x + a.y * b1.x + a.z * b2.x + a.w * b3.x;
            acc[i][1] += a.x * b0.y + a.y * b1.y + a.z * b2.y + a.w * b3.y;
            acc[i][2] += a.x * b0.z + a.y * b1.z + a.z * b2.z + a.w * b3.z;
            acc[i][3] += a.x * b0.w + a.y * b1.w + a.z * b2.w + a.w * b3.w;
        }
    }
    __half* graphA = g_msgA + (size_t)N_MESS * H;
#pragma unroll
    for (int i = 0; i < 8; i++) {
        int m = m0 + warp * 8 + i;
        if (m < N_BONDS) {
            float4 v = make_float4(acc[i][0], acc[i][1], acc[i][2], acc[i][3]);
            *(float4*)&g_binput[(size_t)m * H + n0] = v;
            __half2 h0 = __float22half2_rn(
                make_float2(fmaxf(v.x, 0.f), fmaxf(v.y, 0.f)));
            __half2 h1 = __float22half2_rn(
                make_float2(fmaxf(v.z, 0.f), fmaxf(v.w, 0.f)));
            uint2 p = make_uint2(*reinterpret_cast<uint32_t*>(&h0),
                                 *reinterpret_cast<uint32_t*>(&h1));
            *(uint2*)&graphA[(size_t)m * H + n0] = p;
        }
    }
}

// ---------------------------------------------------------------
// bond iter: dst = relu(binput + gathersum(src)@W_h), fp16 messages.
// 512 threads / 16 warps; warp tile 16x32; regs <= 64 -> 50% occupancy.
__global__ void __launch_bounds__(512, 2)
bond_mma_kernel(const __half* __restrict__ src_msg,
                __half* __restrict__ dst_graph,
                const int* __restrict__ bgraph) {
    extern __shared__ char smem[];
    __nv_bfloat16* Ahi = (__nv_bfloat16*)smem;            // [BMT][ASTR]
    __nv_bfloat16* Alo = Ahi + BMT * ASTR;
    uint2* WH = (uint2*)(Alo + BMT * ASTR);               // [4096]
    uint2* WL = WH + 4096;

    int tid = threadIdx.x, warp = tid >> 5, lane = tid & 31;
    int m0 = blockIdx.x * BMT;

    // stage W fragments (64 KB = 2 x 2048 uint4)
    {
        const uint4* sh = (const uint4*)g_wf_hi;
        const uint4* sl = (const uint4*)g_wf_lo;
        uint4* dh = (uint4*)WH;
        uint4* dl = (uint4*)WL;
        for (int i = tid; i < 2048; i += 512) { dh[i] = sh[i]; dl[i] = sl[i]; }
    }

    // gather: warp -> 4 rows, lane -> cols [4l, 4l+4) (8B fp16 per lane)
#pragma unroll
    for (int i = 0; i < 4; i++) {
        int r = warp * 4 + i;
        int m = m0 + r;
        float4 acc = make_float4(0.f, 0.f, 0.f, 0.f);
        if (m < N_BONDS) {
            const int* bg = &bgraph[m * NBR];
#pragma unroll
            for (int nb = 0; nb < NBR; nb++) {
                int idx = __ldg(&bg[nb]);
                uint2 v = *(const uint2*)&src_msg[(size_t)idx * H + lane * 4];
                acc4h(acc, v);
            }
        }
        float a[4] = {acc.x, acc.y, acc.z, acc.w};
        unsigned short hs[4], ls[4];
#pragma unroll
        for (int j = 0; j < 4; j++) split2(a[j], hs[j], ls[j]);
        *(uint2*)&Ahi[r * ASTR + lane * 4] =
            make_uint2((uint32_t)hs[0] | ((uint32_t)hs[1] << 16),
                       (uint32_t)hs[2] | ((uint32_t)hs[3] << 16));
        *(uint2*)&Alo[r * ASTR + lane * 4] =
            make_uint2((uint32_t)ls[0] | ((uint32_t)ls[1] << 16),
                       (uint32_t)ls[2] | ((uint32_t)ls[3] << 16));
    }
    __syncthreads();

    // MMA: warp (w&3) -> 16-row group, (w>>2) -> 32-col group
    int g = lane >> 2, tig = lane & 3;
    int r0 = (warp & 3) * 16 + g;
    int tbase = (warp >> 2) * 4;
    float c[4][4];
#pragma unroll
    for (int t = 0; t < 4; t++)
#pragma unroll
        for (int j = 0; j < 4; j++) c[t][j] = 0.f;

#pragma unroll
    for (int s = 0; s < 8; s++) {
        int k0 = s * 16 + tig * 2;
        uint32_t ah0 = *(const uint32_t*)&Ahi[(r0    ) * ASTR + k0];
        uint32_t ah1 = *(const uint32_t*)&Ahi[(r0 + 8) * ASTR + k0];
        uint32_t ah2 = *(const uint32_t*)&Ahi[(r0    ) * ASTR + k0 + 8];
        uint32_t ah3 = *(const uint32_t*)&Ahi[(r0 + 8) * ASTR + k0 + 8];
        uint32_t al0 = *(const uint32_t*)&Alo[(r0    ) * ASTR + k0];
        uint32_t al1 = *(const uint32_t*)&Alo[(r0 + 8) * ASTR + k0];
        uint32_t al2 = *(const uint32_t*)&Alo[(r0    ) * ASTR + k0 + 8];
        uint32_t al3 = *(const uint32_t*)&Alo[(r0 + 8) * ASTR + k0 + 8];
#pragma unroll
        for (int t = 0; t < 4; t++) {
            uint2 bh = WH[s * 512 + (tbase + t) * 32 + lane];
            uint2 bl = WL[s * 512 + (tbase + t) * 32 + lane];
            MMA16816(c[t], ah0, ah1, ah2, ah3, bh.x, bh.y);
            MMA16816(c[t], ah0, ah1, ah2, ah3, bl.x, bl.y);
            MMA16816(c[t], al0, al1, al2, al3, bh.x, bh.y);
        }
    }

    // epilogue: +binput (fp32), relu, store fp16
    int mA = m0 + r0;
    int mB = mA + 8;
    int ncol0 = (warp >> 2) * 32 + tig * 2;
#pragma unroll
    for (int t = 0; t < 4; t++) {
        int n0 = ncol0 + t * 8;
        if (mA < N_BONDS) {
            float2 bi = *(const float2*)&g_binput[(size_t)mA * H + n0];
            __half2 o = __float22half2_rn(
                make_float2(fmaxf(bi.x + c[t][0], 0.f),
                            fmaxf(bi.y + c[t][1], 0.f)));
            *(__half2*)&dst_graph[(size_t)mA * H + n0] = o;
        }
        if (mB < N_BONDS) {
            float2 bi = *(const float2*)&g_binput[(size_t)mB * H + n0];
            __half2 o = __float22half2_rn(
                make_float2(fmaxf(bi.x + c[t][2], 0.f),
                            fmaxf(bi.y + c[t][3], 0.f)));
            *(__half2*)&dst_graph[(size_t)mB * H + n0] = o;
        }
    }
}

// ---------------------------------------------------------------
// atom: g_atomh = relu([nei(128)|fatoms(35)|pad] @ Wo_frag + b_o)  via mma
__global__ void __launch_bounds__(256, 2)
atom_mma_kernel(const __half* __restrict__ src_msg,
                const int* __restrict__ agraph,
                const float* __restrict__ fatoms,
                const float* __restrict__ b_o) {
    extern __shared__ char smem[];
    __nv_bfloat16* Ahi = (__nv_bfloat16*)smem;            // [64][ASTRA]
    __nv_bfloat16* Alo = Ahi + 64 * ASTRA;
    uint2* WH = (uint2*)(Alo + 64 * ASTRA);               // [NS_A*512]

    int tid = threadIdx.x, warp = tid >> 5, lane = tid & 31;
    int m0 = blockIdx.x * 64;

    // stage Wo hi fragments: NS_A*512 uint2 = 45056 B = 2816 uint4
    {
        const uint4* sh = (const uint4*)g_wfo_hi;
        uint4* dh = (uint4*)WH;
        for (int i = tid; i < 2816; i += 256) dh[i] = sh[i];
    }

    // nei gather into cols [0,128)  (fp16 messages)
#pragma unroll
    for (int i = 0; i < 8; i++) {
        int r = warp * 8 + i;
        int m = m0 + r;
        float4 acc = make_float4(0.f, 0.f, 0.f, 0.f);
        if (m < N_ATOMS) {
            const int* ag = &agraph[m * NBR];
#pragma unroll
            for (int nb = 0; nb < NBR; nb++) {
                int idx = __ldg(&ag[nb]);
                uint2 v = *(const uint2*)&src_msg[(size_t)idx * H + lane * 4];
                acc4h(acc, v);
            }
        }
        float a[4] = {acc.x, acc.y, acc.z, acc.w};
        unsigned short hs[4], ls[4];
#pragma unroll
        for (int j = 0; j < 4; j++) split2(a[j], hs[j], ls[j]);
        *(uint2*)&Ahi[r * ASTRA + lane * 4] =
            make_uint2((uint32_t)hs[0] | ((uint32_t)hs[1] << 16),
                       (uint32_t)hs[2] | ((uint32_t)hs[3] << 16));
        *(uint2*)&Alo[r * ASTRA + lane * 4] =
            make_uint2((uint32_t)ls[0] | ((uint32_t)ls[1] << 16),
                       (uint32_t)ls[2] | ((uint32_t)ls[3] << 16));
    }
    // fatoms into cols [128,163), zero pad [163,176)
    for (int i = tid; i < 64 * 48; i += 256) {
        int r = i / 48, cc = 128 + (i % 48);
        int m = m0 + r;
        float v = (cc < 163 && m < N_ATOMS)
                  ? fatoms[(size_t)m * AF + (cc - 128)] : 0.f;
        unsigned short h, l;
        split2(v, h, l);
        Ahi[r * ASTRA + cc] = __ushort_as_bfloat16(h);
        Alo[r * ASTRA + cc] = __ushort_as_bfloat16(l);
    }
    __syncthreads();

    int g = lane >> 2, tig = lane & 3;
    int r0 = (warp & 3) * 16 + g;
    int tbase = (warp >> 2) * 8;
    float c[8][4];
#pragma unroll
    for (int t = 0; t < 8; t++)
#pragma unroll
        for (int j = 0; j < 4; j++) c[t][j] = 0.f;

#pragma unroll
    for (int s = 0; s < NS_A; s++) {
        int k0 = s * 16 + tig * 2;
        uint32_t ah0 = *(const uint32_t*)&Ahi[(r0    ) * ASTRA + k0];
        uint32_t ah1 = *(const uint32_t*)&Ahi[(r0 + 8) * ASTRA + k0];
        uint32_t ah2 = *(const uint32_t*)&Ahi[(r0    ) * ASTRA + k0 + 8];
        uint32_t ah3 = *(const uint32_t*)&Ahi[(r0 + 8) * ASTRA + k0 + 8];
        uint32_t al0 = *(const uint32_t*)&Alo[(r0    ) * ASTRA + k0];
        uint32_t al1 = *(const uint32_t*)&Alo[(r0 + 8) * ASTRA + k0];
        uint32_t al2 = *(const uint32_t*)&Alo[(r0    ) * ASTRA + k0 + 8];
        uint32_t al3 = *(const uint32_t*)&Alo[(r0 + 8) * ASTRA + k0 + 8];
#pragma unroll
        for (int t = 0; t < 8; t++) {
            int fi = s * 512 + (tbase + t) * 32 + lane;
            uint2 bh = WH[fi];
            uint2 bl = __ldg(&g_wfo_lo[fi]);
            MMA16816(c[t], ah0, ah1, ah2, ah3, bh.x, bh.y);
            MMA16816(c[t], ah0, ah1, ah2, ah3, bl.x, bl.y);
            MMA16816(c[t], al0, al1, al2, al3, bh.x, bh.y);
        }
    }

    int mA = m0 + r0;
    int mB = mA + 8;
    int ncol0 = (warp >> 2) * 64 + tig * 2;
#pragma unroll
    for (int t = 0; t < 8; t++) {
        int n0 = ncol0 + t * 8;
        float2 bo = *(const float2*)&b_o[n0];
        if (mA < N_ATOMS) {
            float2 o = make_float2(fmaxf(bo.x + c[t][0], 0.f),
                                   fmaxf(bo.y + c[t][1], 0.f));
            *(float2*)&g_atomh[(size_t)mA * H + n0] = o;
        }
        if (mB < N_ATOMS) {
            float2 o = make_float2(fmaxf(bo.x + c[t][2], 0.f),
                                   fmaxf(bo.y + c[t][3], 0.f));
            *(float2*)&g_atomh[(size_t)mB * H + n0] = o;
        }
    }
}

// ---------------------------------------------------------------
__device__ __forceinline__ int lowerb(const int* __restrict__ a, int n, int key) {
    int lo = 0, hi = n;
    while (lo < hi) {
        int mid = (lo + hi) >> 1;
        if (a[mid] < key) lo = mid + 1; else hi = mid;
    }
    return lo;
}

__global__ void pool_kernel(const int* __restrict__ mol_ids,
                            float* __restrict__ out) {
    int mol = blockIdx.x;
    int tid = threadIdx.x;
    int lo = lowerb(mol_ids, N_ATOMS, mol);
    int hi = lowerb(mol_ids, N_ATOMS, mol + 1);
    float s = 0.f;
    for (int a = lo; a < hi; a++)
        s += g_atomh[(size_t)a * H + tid];
    int cnt = hi - lo;
    out[(size_t)mol * H + tid] = cnt ? s / (float)cnt : 0.f;
}

// ---------------------------------------------------------------
extern "C" void kernel_launch(void* const* d_in, const int* in_sizes, int n_in,
                              void* d_out, int out_size) {
    const float *fatoms = nullptr, *fbonds = nullptr, *tree = nullptr;
    const float *W_i = nullptr, *W_h = nullptr, *W_o = nullptr, *b_o = nullptr;
    const int *agraph = nullptr, *bgraph = nullptr, *mol_ids = nullptr;
    for (int i = 0; i < n_in; i++) {
        switch (in_sizes[i]) {
            case 3500000: fatoms  = (const float*)d_in[i]; break;   // 100000*35
            case 8800000: fbonds  = (const float*)d_in[i]; break;   // 220000*40
            case 2560000: tree    = (const float*)d_in[i]; break;   // 20000*128
            case 1000000: agraph  = (const int*)d_in[i];   break;   // 100000*10
            case 2200000: bgraph  = (const int*)d_in[i];   break;   // 220000*10
            case 100000:  mol_ids = (const int*)d_in[i];   break;
            case 5120:    W_i     = (const float*)d_in[i]; break;   // 40*128
            case 16384:   W_h     = (const float*)d_in[i]; break;   // 128*128
            case 20864:   W_o     = (const float*)d_in[i]; break;   // 163*128
            case 128:     b_o     = (const float*)d_in[i]; break;
        }
    }

    const int BIN_SMEM  = (TM * BF + BF * H) * 4;
    const int BOND_SMEM = BMT * ASTR * 2 * 2 + 4096 * 8 * 2;   // 100352
    const int ATOM_SMEM = 64 * ASTRA * 2 * 2 + NS_A * 512 * 8; // 92160
    cudaFuncSetAttribute(bond_mma_kernel,
                         cudaFuncAttributeMaxDynamicSharedMemorySize, BOND_SMEM);
    cudaFuncSetAttribute(atom_mma_kernel,
                         cudaFuncAttributeMaxDynamicSharedMemorySize, ATOM_SMEM);

    __half *msgA, *msgB;
    cudaGetSymbolAddress((void**)&msgA, g_msgA);
    cudaGetSymbolAddress((void**)&msgB, g_msgB);

    int tc_blocks = (N_MESS * H / 4 + 255) / 256;
    tree_copy_kernel<<<tc_blocks, 256>>>(tree);
    prep_w_kernel<<<(8 * 16 * 32 + 255) / 256, 256>>>(W_h);
    prep_wo_kernel<<<(NS_A * 16 * 32 + 255) / 256, 256>>>(W_o);

    int grid_bin = (N_BONDS + TM - 1) / TM;
    binput_kernel<<<grid_bin, TB, BIN_SMEM>>>(fbonds, W_i);

    __half* src = msgA;
    __half* dst = msgB;
    int grid_mma = (N_BONDS + BMT - 1) / BMT;   // 3438
    for (int it = 0; it < 5; it++) {            // DEPTH-1
        bond_mma_kernel<<<grid_mma, 512, BOND_SMEM>>>(
            src, dst + (size_t)N_MESS * H, bgraph);
        __half* t = src; src = dst; dst = t;
    }

    int grid_a = (N_ATOMS + 63) / 64;           // 1563
    atom_mma_kernel<<<grid_a, 256, ATOM_SMEM>>>(src, agraph, fatoms, b_o);

    pool_kernel<<<N_MOLS, H>>>(mol_ids, (float*)d_out);
}

// round 13
// speedup vs baseline: 1.7502x; 1.0331x over previous
#include <cuda_runtime.h>
#include <cuda_bf16.h>
#include <cuda_fp16.h>
#include <cstdint>

#define H       128
#define NBR     10
#define AF      35
#define BF      40            // ATOM_FDIM + BOND_FDIM
#define N_ATOMS 100000
#define N_BONDS 220000
#define N_MESS  20000
#define N_MOLS  2000
#define MSG_ROWS (N_MESS + N_BONDS)

// bond mma kernel tiling
#define BMT     64            // rows per block
#define ASTR    136           // A row stride (bf16), conflict-free fragments
// atom mma kernel tiling
#define ASTRA   184           // A row stride (bf16)
#define NS_A    11            // k-steps for atom
// binput mma kernel tiling
#define ASTRB   56            // A row stride (bf16) for K=48
#define NS_B    3             // k-steps for binput (K padded 40->48)

// ---- scratch (device globals: allocation-free kernel_launch) ----
// messages + binput stored fp16: halves gather/epilogue traffic; values
// are summed/accumulated in fp32 and hi/lo-split for the MMA.
__device__ __half g_msgA[(size_t)MSG_ROWS * H];
__device__ __half g_msgB[(size_t)MSG_ROWS * H];
__device__ __half g_binput[(size_t)N_BONDS * H];
__device__ float g_atomh[(size_t)N_ATOMS * H];
// W_h fragments: [kstep 8][ntile 16][lane 32] uint2, hi & lo planes
__device__ uint2 g_wf_hi[8 * 16 * 32];
__device__ uint2 g_wf_lo[8 * 16 * 32];
// W_o (reordered+padded) fragments: [kstep 11][ntile 16][lane 32]
__device__ uint2 g_wfo_hi[NS_A * 16 * 32];
__device__ uint2 g_wfo_lo[NS_A * 16 * 32];
// W_i (padded 40->48) fragments: [kstep 3][ntile 16][lane 32]
__device__ uint2 g_wfi_hi[NS_B * 16 * 32];
__device__ uint2 g_wfi_lo[NS_B * 16 * 32];

#define MMA16816(c, a0, a1, a2, a3, b0, b1) \
    asm volatile("mma.sync.aligned.m16n8k16.row.col.f32.bf16.bf16.f32 " \
        "{%0,%1,%2,%3}, {%4,%5,%6,%7}, {%8,%9}, {%0,%1,%2,%3};" \
        : "+f"((c)[0]), "+f"((c)[1]), "+f"((c)[2]), "+f"((c)[3]) \
        : "r"(a0), "r"(a1), "r"(a2), "r"(a3), "r"(b0), "r"(b1))

__device__ __forceinline__ unsigned short bf16hi(float v) {
    return __bfloat16_as_ushort(__float2bfloat16_rn(v));
}
__device__ __forceinline__ void split2(float v, unsigned short& h, unsigned short& l) {
    h = bf16hi(v);
    l = bf16hi(v - __bfloat162float(__ushort_as_bfloat16(h)));
}
// accumulate 4 fp16 (as uint2) into float4
__device__ __forceinline__ void acc4h(float4& acc, uint2 v) {
    float2 f0 = __half22float2(*reinterpret_cast<__half2*>(&v.x));
    float2 f1 = __half22float2(*reinterpret_cast<__half2*>(&v.y));
    acc.x += f0.x; acc.y += f0.y; acc.z += f1.x; acc.w += f1.y;
}

// ---------------------------------------------------------------
__global__ void tree_copy_kernel(const float* __restrict__ tree) {
    int i = blockIdx.x * blockDim.x + threadIdx.x;
    int n4 = N_MESS * H / 4;
    if (i < n4) {
        float4 v = ((const float4*)tree)[i];
        __half2 h0 = __float22half2_rn(make_float2(v.x, v.y));
        __half2 h1 = __float22half2_rn(make_float2(v.z, v.w));
        uint2 p = make_uint2(*reinterpret_cast<uint32_t*>(&h0),
                             *reinterpret_cast<uint32_t*>(&h1));
        ((uint2*)g_msgA)[i] = p;
        ((uint2*)g_msgB)[i] = p;
    }
}

// ---------------------------------------------------------------
// W_h [k][n] -> bf16 hi/lo B-fragments (m16n8k16):
// i = s*512 + t*32 + lane; g=lane>>2, tig=lane&3; n=t*8+g; k0=s*16+tig*2
__global__ void prep_w_kernel(const float* __restrict__ W_h) {
    int i = blockIdx.x * blockDim.x + threadIdx.x;
    if (i >= 8 * 16 * 32) return;
    int lane = i & 31, t = (i >> 5) & 15, s = i >> 9;
    int g = lane >> 2, tig = lane & 3;
    int n = t * 8 + g;
    int k0 = s * 16 + tig * 2;
    float w[4] = { W_h[(k0 + 0) * H + n], W_h[(k0 + 1) * H + n],
                   W_h[(k0 + 8) * H + n], W_h[(k0 + 9) * H + n] };
    unsigned short h[4], l[4];
#pragma unroll
    for (int j = 0; j < 4; j++) split2(w[j], h[j], l[j]);
    g_wf_hi[i] = make_uint2((uint32_t)h[0] | ((uint32_t)h[1] << 16),
                            (uint32_t)h[2] | ((uint32_t)h[3] << 16));
    g_wf_lo[i] = make_uint2((uint32_t)l[0] | ((uint32_t)l[1] << 16),
                            (uint32_t)l[2] | ((uint32_t)l[3] << 16));
}

// W_o reordered (A col k: k<128 -> W_o row 35+k; 128..162 -> row k-128; else 0)
__device__ __forceinline__ float wo_val(const float* W_o, int k, int n) {
    if (k < 128)  return W_o[(size_t)(35 + k) * H + n];
    if (k < 163)  return W_o[(size_t)(k - 128) * H + n];
    return 0.f;
}
__global__ void prep_wo_kernel(const float* __restrict__ W_o) {
    int i = blockIdx.x * blockDim.x + threadIdx.x;
    if (i >= NS_A * 16 * 32) return;
    int lane = i & 31, t = (i >> 5) & 15, s = i >> 9;
    int g = lane >> 2, tig = lane & 3;
    int n = t * 8 + g;
    int k0 = s * 16 + tig * 2;
    float w[4] = { wo_val(W_o, k0 + 0, n), wo_val(W_o, k0 + 1, n),
                   wo_val(W_o, k0 + 8, n), wo_val(W_o, k0 + 9, n) };
    unsigned short h[4], l[4];
#pragma unroll
    for (int j = 0; j < 4; j++) split2(w[j], h[j], l[j]);
    g_wfo_hi[i] = make_uint2((uint32_t)h[0] | ((uint32_t)h[1] << 16),
                             (uint32_t)h[2] | ((uint32_t)h[3] << 16));
    g_wfo_lo[i] = make_uint2((uint32_t)l[0] | ((uint32_t)l[1] << 16),
                             (uint32_t)l[2] | ((uint32_t)l[3] << 16));
}

// W_i [k][n], K padded 40->48 with zero rows
__global__ void prep_wi_kernel(const float* __restrict__ W_i) {
    int i = blockIdx.x * blockDim.x + threadIdx.x;
    if (i >= NS_B * 16 * 32) return;
    int lane = i & 31, t = (i >> 5) & 15, s = i >> 9;
    int g = lane >> 2, tig = lane & 3;
    int n = t * 8 + g;
    int k0 = s * 16 + tig * 2;
    float w[4];
    int ks[4] = { k0, k0 + 1, k0 + 8, k0 + 9 };
#pragma unroll
    for (int j = 0; j < 4; j++)
        w[j] = (ks[j] < BF) ? W_i[(size_t)ks[j] * H + n] : 0.f;
    unsigned short h[4], l[4];
#pragma unroll
    for (int j = 0; j < 4; j++) split2(w[j], h[j], l[j]);
    g_wfi_hi[i] = make_uint2((uint32_t)h[0] | ((uint32_t)h[1] << 16),
                             (uint32_t)h[2] | ((uint32_t)h[3] << 16));
    g_wfi_lo[i] = make_uint2((uint32_t)l[0] | ((uint32_t)l[1] << 16),
                             (uint32_t)l[2] | ((uint32_t)l[3] << 16));
}

// ---------------------------------------------------------------
// binput = fbonds @ W_i (fp16 out); msgA graph part = relu (fp16)   via mma
__global__ void __launch_bounds__(256, 2)
binput_mma_kernel(const float* __restrict__ fbonds) {
    extern __shared__ char smem[];
    __nv_bfloat16* Ahi = (__nv_bfloat16*)smem;            // [64][ASTRB]
    __nv_bfloat16* Alo = Ahi + 64 * ASTRB;
    uint2* WH = (uint2*)(Alo + 64 * ASTRB);               // [NS_B*512]
    uint2* WL = WH + NS_B * 512;

    int tid = threadIdx.x, warp = tid >> 5, lane = tid & 31;
    int m0 = blockIdx.x * 64;

    // stage W_i fragments: NS_B*512 uint2 = 12288 B = NS_B*256 uint4 per plane
    {
        const uint4* sh = (const uint4*)g_wfi_hi;
        const uint4* sl = (const uint4*)g_wfi_lo;
        uint4* dh = (uint4*)WH;
        uint4* dl = (uint4*)WL;
        for (int i = tid; i < NS_B * 256; i += 256) { dh[i] = sh[i]; dl[i] = sl[i]; }
    }

    // load fbonds rows, split hi/lo; cols [40,48) zero
    for (int i = tid; i < 64 * 48; i += 256) {
        int r = i / 48, c = i % 48;
        int m = m0 + r;
        float v = (c < BF && m < N_BONDS) ? fbonds[(size_t)m * BF + c] : 0.f;
        unsigned short h, l;
        split2(v, h, l);
        Ahi[r * ASTRB + c] = __ushort_as_bfloat16(h);
        Alo[r * ASTRB + c] = __ushort_as_bfloat16(l);
    }
    __syncthreads();

    int g = lane >> 2, tig = lane & 3;
    int r0 = (warp & 3) * 16 + g;
    int tbase = (warp >> 2) * 8;
    float c[8][4];
#pragma unroll
    for (int t = 0; t < 8; t++)
#pragma unroll
        for (int j = 0; j < 4; j++) c[t][j] = 0.f;

#pragma unroll
    for (int s = 0; s < NS_B; s++) {
        int k0 = s * 16 + tig * 2;
        uint32_t ah0 = *(const uint32_t*)&Ahi[(r0    ) * ASTRB + k0];
        uint32_t ah1 = *(const uint32_t*)&Ahi[(r0 + 8) * ASTRB + k0];
        uint32_t ah2 = *(const uint32_t*)&Ahi[(r0    ) * ASTRB + k0 + 8];
        uint32_t ah3 = *(const uint32_t*)&Ahi[(r0 + 8) * ASTRB + k0 + 8];
        uint32_t al0 = *(const uint32_t*)&Alo[(r0    ) * ASTRB + k0];
        uint32_t al1 = *(const uint32_t*)&Alo[(r0 + 8) * ASTRB + k0];
        uint32_t al2 = *(const uint32_t*)&Alo[(r0    ) * ASTRB + k0 + 8];
        uint32_t al3 = *(const uint32_t*)&Alo[(r0 + 8) * ASTRB + k0 + 8];
#pragma unroll
        for (int t = 0; t < 8; t++) {
            int fi = s * 512 + (tbase + t) * 32 + lane;
            uint2 bh = WH[fi];
            uint2 bl = WL[fi];
            MMA16816(c[t], ah0, ah1, ah2, ah3, bh.x, bh.y);
            MMA16816(c[t], ah0, ah1, ah2, ah3, bl.x, bl.y);
            MMA16816(c[t], al0, al1, al2, al3, bh.x, bh.y);
        }
    }

    __half* graphA = g_msgA + (size_t)N_MESS * H;
    int mA = m0 + r0;
    int mB = mA + 8;
    int ncol0 = (warp >> 2) * 64 + tig * 2;
#pragma unroll
    for (int t = 0; t < 8; t++) {
        int n0 = ncol0 + t * 8;
        if (mA < N_BONDS) {
            __half2 b = __float22half2_rn(make_float2(c[t][0], c[t][1]));
            *(__half2*)&g_binput[(size_t)mA * H + n0] = b;
            __half2 r = __float22half2_rn(
                make_float2(fmaxf(c[t][0], 0.f), fmaxf(c[t][1], 0.f)));
            *(__half2*)&graphA[(size_t)mA * H + n0] = r;
        }
        if (mB < N_BONDS) {
            __half2 b = __float22half2_rn(make_float2(c[t][2], c[t][3]));
            *(__half2*)&g_binput[(size_t)mB * H + n0] = b;
            __half2 r = __float22half2_rn(
                make_float2(fmaxf(c[t][2], 0.f), fmaxf(c[t][3], 0.f)));
            *(__half2*)&graphA[(size_t)mB * H + n0] = r;
        }
    }
}

// ---------------------------------------------------------------
// bond iter: dst = relu(binput + gathersum(src)@W_h), fp16 messages+binput.
// 512 threads / 16 warps; warp tile 16x32; regs <= 64 -> 50% occupancy.
__global__ void __launch_bounds__(512, 2)
bond_mma_kernel(const __half* __restrict__ src_msg,
                __half* __restrict__ dst_graph,
                const int* __restrict__ bgraph) {
    extern __shared__ char smem[];
    __nv_bfloat16* Ahi = (__nv_bfloat16*)smem;            // [BMT][ASTR]
    __nv_bfloat16* Alo = Ahi + BMT * ASTR;
    uint2* WH = (uint2*)(Alo + BMT * ASTR);               // [4096]
    uint2* WL = WH + 4096;

    int tid = threadIdx.x, warp = tid >> 5, lane = tid & 31;
    int m0 = blockIdx.x * BMT;

    // stage W fragments (64 KB = 2 x 2048 uint4)
    {
        const uint4* sh = (const uint4*)g_wf_hi;
        const uint4* sl = (const uint4*)g_wf_lo;
        uint4* dh = (uint4*)WH;
        uint4* dl = (uint4*)WL;
        for (int i = tid; i < 2048; i += 512) { dh[i] = sh[i]; dl[i] = sl[i]; }
    }

    // gather: warp -> 4 rows, lane -> cols [4l, 4l+4) (8B fp16 per lane)
#pragma unroll
    for (int i = 0; i < 4; i++) {
        int r = warp * 4 + i;
        int m = m0 + r;
        float4 acc = make_float4(0.f, 0.f, 0.f, 0.f);
        if (m < N_BONDS) {
            const int* bg = &bgraph[m * NBR];
#pragma unroll
            for (int nb = 0; nb < NBR; nb++) {
                int idx = __ldg(&bg[nb]);
                uint2 v = *(const uint2*)&src_msg[(size_t)idx * H + lane * 4];
                acc4h(acc, v);
            }
        }
        float a[4] = {acc.x, acc.y, acc.z, acc.w};
        unsigned short hs[4], ls[4];
#pragma unroll
        for (int j = 0; j < 4; j++) split2(a[j], hs[j], ls[j]);
        *(uint2*)&Ahi[r * ASTR + lane * 4] =
            make_uint2((uint32_t)hs[0] | ((uint32_t)hs[1] << 16),
                       (uint32_t)hs[2] | ((uint32_t)hs[3] << 16));
        *(uint2*)&Alo[r * ASTR + lane * 4] =
            make_uint2((uint32_t)ls[0] | ((uint32_t)ls[1] << 16),
                       (uint32_t)ls[2] | ((uint32_t)ls[3] << 16));
    }
    __syncthreads();

    // MMA: warp (w&3) -> 16-row group, (w>>2) -> 32-col group
    int g = lane >> 2, tig = lane & 3;
    int r0 = (warp & 3) * 16 + g;
    int tbase = (warp >> 2) * 4;
    float c[4][4];
#pragma unroll
    for (int t = 0; t < 4; t++)
#pragma unroll
        for (int j = 0; j < 4; j++) c[t][j] = 0.f;

#pragma unroll
    for (int s = 0; s < 8; s++) {
        int k0 = s * 16 + tig * 2;
        uint32_t ah0 = *(const uint32_t*)&Ahi[(r0    ) * ASTR + k0];
        uint32_t ah1 = *(const uint32_t*)&Ahi[(r0 + 8) * ASTR + k0];
        uint32_t ah2 = *(const uint32_t*)&Ahi[(r0    ) * ASTR + k0 + 8];
        uint32_t ah3 = *(const uint32_t*)&Ahi[(r0 + 8) * ASTR + k0 + 8];
        uint32_t al0 = *(const uint32_t*)&Alo[(r0    ) * ASTR + k0];
        uint32_t al1 = *(const uint32_t*)&Alo[(r0 + 8) * ASTR + k0];
        uint32_t al2 = *(const uint32_t*)&Alo[(r0    ) * ASTR + k0 + 8];
        uint32_t al3 = *(const uint32_t*)&Alo[(r0 + 8) * ASTR + k0 + 8];
#pragma unroll
        for (int t = 0; t < 4; t++) {
            uint2 bh = WH[s * 512 + (tbase + t) * 32 + lane];
            uint2 bl = WL[s * 512 + (tbase + t) * 32 + lane];
            MMA16816(c[t], ah0, ah1, ah2, ah3, bh.x, bh.y);
            MMA16816(c[t], ah0, ah1, ah2, ah3, bl.x, bl.y);
            MMA16816(c[t], al0, al1, al2, al3, bh.x, bh.y);
        }
    }

    // epilogue: +binput (fp16), relu, store fp16
    int mA = m0 + r0;
    int mB = mA + 8;
    int ncol0 = (warp >> 2) * 32 + tig * 2;
#pragma unroll
    for (int t = 0; t < 4; t++) {
        int n0 = ncol0 + t * 8;
        if (mA < N_BONDS) {
            float2 bi = __half22float2(
                *(const __half2*)&g_binput[(size_t)mA * H + n0]);
            __half2 o = __float22half2_rn(
                make_float2(fmaxf(bi.x + c[t][0], 0.f),
                            fmaxf(bi.y + c[t][1], 0.f)));
            *(__half2*)&dst_graph[(size_t)mA * H + n0] = o;
        }
        if (mB < N_BONDS) {
            float2 bi = __half22float2(
                *(const __half2*)&g_binput[(size_t)mB * H + n0]);
            __half2 o = __float22half2_rn(
                make_float2(fmaxf(bi.x + c[t][2], 0.f),
                            fmaxf(bi.y + c[t][3], 0.f)));
            *(__half2*)&dst_graph[(size_t)mB * H + n0] = o;
        }
    }
}

// ---------------------------------------------------------------
// atom: g_atomh = relu([nei(128)|fatoms(35)|pad] @ Wo_frag + b_o)  via mma
__global__ void __launch_bounds__(256, 2)
atom_mma_kernel(const __half* __restrict__ src_msg,
                const int* __restrict__ agraph,
                const float* __restrict__ fatoms,
                const float* __restrict__ b_o) {
    extern __shared__ char smem[];
    __nv_bfloat16* Ahi = (__nv_bfloat16*)smem;            // [64][ASTRA]
    __nv_bfloat16* Alo = Ahi + 64 * ASTRA;
    uint2* WH = (uint2*)(Alo + 64 * ASTRA);               // [NS_A*512]

    int tid = threadIdx.x, warp = tid >> 5, lane = tid & 31;
    int m0 = blockIdx.x * 64;

    // stage Wo hi fragments: NS_A*512 uint2 = 45056 B = NS_A*256 = 2816 uint4
    {
        const uint4* sh = (const uint4*)g_wfo_hi;
        uint4* dh = (uint4*)WH;
        for (int i = tid; i < NS_A * 256; i += 256) dh[i] = sh[i];
    }

    // nei gather into cols [0,128)  (fp16 messages)
#pragma unroll
    for (int i = 0; i < 8; i++) {
        int r = warp * 8 + i;
        int m = m0 + r;
        float4 acc = make_float4(0.f, 0.f, 0.f, 0.f);
        if (m < N_ATOMS) {
            const int* ag = &agraph[m * NBR];
#pragma unroll
            for (int nb = 0; nb < NBR; nb++) {
                int idx = __ldg(&ag[nb]);
                uint2 v = *(const uint2*)&src_msg[(size_t)idx * H + lane * 4];
                acc4h(acc, v);
            }
        }
        float a[4] = {acc.x, acc.y, acc.z, acc.w};
        unsigned short hs[4], ls[4];
#pragma unroll
        for (int j = 0; j < 4; j++) split2(a[j], hs[j], ls[j]);
        *(uint2*)&Ahi[r * ASTRA + lane * 4] =
            make_uint2((uint32_t)hs[0] | ((uint32_t)hs[1] << 16),
                       (uint32_t)hs[2] | ((uint32_t)hs[3] << 16));
        *(uint2*)&Alo[r * ASTRA + lane * 4] =
            make_uint2((uint32_t)ls[0] | ((uint32_t)ls[1] << 16),
                       (uint32_t)ls[2] | ((uint32_t)ls[3] << 16));
    }
    // fatoms into cols [128,163), zero pad [163,176)
    for (int i = tid; i < 64 * 48; i += 256) {
        int r = i / 48, cc = 128 + (i % 48);
        int m = m0 + r;
        float v = (cc < 163 && m < N_ATOMS)
                  ? fatoms[(size_t)m * AF + (cc - 128)] : 0.f;
        unsigned short h, l;
        split2(v, h, l);
        Ahi[r * ASTRA + cc] = __ushort_as_bfloat16(h);
        Alo[r * ASTRA + cc] = __ushort_as_bfloat16(l);
    }
    __syncthreads();

    int g = lane >> 2, tig = lane & 3;
    int r0 = (warp & 3) * 16 + g;
    int tbase = (warp >> 2) * 8;
    float c[8][4];
#pragma unroll
    for (int t = 0; t < 8; t++)
#pragma unroll
        for (int j = 0; j < 4; j++) c[t][j] = 0.f;

#pragma unroll
    for (int s = 0; s < NS_A; s++) {
        int k0 = s * 16 + tig * 2;
        uint32_t ah0 = *(const uint32_t*)&Ahi[(r0    ) * ASTRA + k0];
        uint32_t ah1 = *(const uint32_t*)&Ahi[(r0 + 8) * ASTRA + k0];
        uint32_t ah2 = *(const uint32_t*)&Ahi[(r0    ) * ASTRA + k0 + 8];
        uint32_t ah3 = *(const uint32_t*)&Ahi[(r0 + 8) * ASTRA + k0 + 8];
        uint32_t al0 = *(const uint32_t*)&Alo[(r0    ) * ASTRA + k0];
        uint32_t al1 = *(const uint32_t*)&Alo[(r0 + 8) * ASTRA + k0];
        uint32_t al2 = *(const uint32_t*)&Alo[(r0    ) * ASTRA + k0 + 8];
        uint32_t al3 = *(const uint32_t*)&Alo[(r0 + 8) * ASTRA + k0 + 8];
#pragma unroll
        for (int t = 0; t < 8; t++) {
            int fi = s * 512 + (tbase + t) * 32 + lane;
            uint2 bh = WH[fi];
            uint2 bl = __ldg(&g_wfo_lo[fi]);
            MMA16816(c[t], ah0, ah1, ah2, ah3, bh.x, bh.y);
            MMA16816(c[t], ah0, ah1, ah2, ah3, bl.x, bl.y);
            MMA16816(c[t], al0, al1, al2, al3, bh.x, bh.y);
        }
    }

    int mA = m0 + r0;
    int mB = mA + 8;
    int ncol0 = (warp >> 2) * 64 + tig * 2;
#pragma unroll
    for (int t = 0; t < 8; t++) {
        int n0 = ncol0 + t * 8;
        float2 bo = *(const float2*)&b_o[n0];
        if (mA < N_ATOMS) {
            float2 o = make_float2(fmaxf(bo.x + c[t][0], 0.f),
                                   fmaxf(bo.y + c[t][1], 0.f));
            *(float2*)&g_atomh[(size_t)mA * H + n0] = o;
        }
        if (mB < N_ATOMS) {
            float2 o = make_float2(fmaxf(bo.x + c[t][2], 0.f),
                                   fmaxf(bo.y + c[t][3], 0.f));
            *(float2*)&g_atomh[(size_t)mB * H + n0] = o;
        }
    }
}

// ---------------------------------------------------------------
__device__ __forceinline__ int lowerb(const int* __restrict__ a, int n, int key) {
    int lo = 0, hi = n;
    while (lo < hi) {
        int mid = (lo + hi) >> 1;
        if (a[mid] < key) lo = mid + 1; else hi = mid;
    }
    return lo;
}

__global__ void pool_kernel(const int* __restrict__ mol_ids,
                            float* __restrict__ out) {
    int mol = blockIdx.x;
    int tid = threadIdx.x;
    int lo = lowerb(mol_ids, N_ATOMS, mol);
    int hi = lowerb(mol_ids, N_ATOMS, mol + 1);
    float s = 0.f;
    for (int a = lo; a < hi; a++)
        s += g_atomh[(size_t)a * H + tid];
    int cnt = hi - lo;
    out[(size_t)mol * H + tid] = cnt ? s / (float)cnt : 0.f;
}

// ---------------------------------------------------------------
extern "C" void kernel_launch(void* const* d_in, const int* in_sizes, int n_in,
                              void* d_out, int out_size) {
    const float *fatoms = nullptr, *fbonds = nullptr, *tree = nullptr;
    const float *W_i = nullptr, *W_h = nullptr, *W_o = nullptr, *b_o = nullptr;
    const int *agraph = nullptr, *bgraph = nullptr, *mol_ids = nullptr;
    for (int i = 0; i < n_in; i++) {
        switch (in_sizes[i]) {
            case 3500000: fatoms  = (const float*)d_in[i]; break;   // 100000*35
            case 8800000: fbonds  = (const float*)d_in[i]; break;   // 220000*40
            case 2560000: tree    = (const float*)d_in[i]; break;   // 20000*128
            case 1000000: agraph  = (const int*)d_in[i];   break;   // 100000*10
            case 2200000: bgraph  = (const int*)d_in[i];   break;   // 220000*10
            case 100000:  mol_ids = (const int*)d_in[i];   break;
            case 5120:    W_i     = (const float*)d_in[i]; break;   // 40*128
            case 16384:   W_h     = (const float*)d_in[i]; break;   // 128*128
            case 20864:   W_o     = (const float*)d_in[i]; break;   // 163*128
            case 128:     b_o     = (const float*)d_in[i]; break;
        }
    }

    const int BOND_SMEM = BMT * ASTR * 2 * 2 + 4096 * 8 * 2;   // 100352
    const int ATOM_SMEM = 64 * ASTRA * 2 * 2 + NS_A * 512 * 8; // 92160
    const int BINM_SMEM = 64 * ASTRB * 2 * 2 + NS_B * 512 * 8 * 2; // 38912
    cudaFuncSetAttribute(bond_mma_kernel,
                         cudaFuncAttributeMaxDynamicSharedMemorySize, BOND_SMEM);
    cudaFuncSetAttribute(atom_mma_kernel,
                         cudaFuncAttributeMaxDynamicSharedMemorySize, ATOM_SMEM);

    __half *msgA, *msgB;
    cudaGetSymbolAddress((void**)&msgA, g_msgA);
    cudaGetSymbolAddress((void**)&msgB, g_msgB);

    int tc_blocks = (N_MESS * H / 4 + 255) / 256;
    tree_copy_kernel<<<tc_blocks, 256>>>(tree);
    prep_w_kernel<<<(8 * 16 * 32 + 255) / 256, 256>>>(W_h);
    prep_wo_kernel<<<(NS_A * 16 * 32 + 255) / 256, 256>>>(W_o);
    prep_wi_kernel<<<(NS_B * 16 * 32 + 255) / 256, 256>>>(W_i);

    int grid_bin = (N_BONDS + 63) / 64;   // 3438
    binput_mma_kernel<<<grid_bin, 256, BINM_SMEM>>>(fbonds);

    __half* src = msgA;
    __half* dst = msgB;
    int grid_mma = (N_BONDS + BMT - 1) / BMT;   // 3438
    for (int it = 0; it < 5; it++) {            // DEPTH-1
        bond_mma_kernel<<<grid_mma, 512, BOND_SMEM>>>(
            src, dst + (size_t)N_MESS * H, bgraph);
        __half* t = src; src = dst; dst = t;
    }

    int grid_a = (N_ATOMS + 63) / 64;           // 1563
    atom_mma_kernel<<<grid_a, 256, ATOM_SMEM>>>(src, agraph, fatoms, b_o);

    pool_kernel<<<N_MOLS, H>>>(mol_ids, (float*)d_out);
}

// round 14
// speedup vs baseline: 1.9451x; 1.1114x over previous
#include <cuda_runtime.h>
#include <cuda_bf16.h>
#include <cuda_fp16.h>
#include <cstdint>

#define H       128
#define NBR     10
#define AF      35
#define BF      40            // ATOM_FDIM + BOND_FDIM
#define N_ATOMS 100000
#define N_BONDS 220000
#define N_MESS  20000
#define N_MOLS  2000
#define MSG_ROWS (N_MESS + N_BONDS)

// bond mma kernel tiling
#define BMT     64            // rows per block
#define ASTR    136           // A row stride (fp16), conflict-free fragments
// atom mma kernel tiling
#define ASTRA   184           // A row stride (fp16)
#define NS_A    11            // k-steps for atom
// binput mma kernel tiling (bf16 3-term, unchanged)
#define ASTRB   56            // A row stride (bf16) for K=48
#define NS_B    3             // k-steps for binput (K padded 40->48)

// ---- scratch (device globals: allocation-free kernel_launch) ----
__device__ __half g_msgA[(size_t)MSG_ROWS * H];
__device__ __half g_msgB[(size_t)MSG_ROWS * H];
__device__ __half g_binput[(size_t)N_BONDS * H];
__device__ float g_atomh[(size_t)N_ATOMS * H];
// W_h fragments (fp16 hi/lo): [kstep 8][ntile 16][lane 32] uint2
__device__ uint2 g_wf_hi[8 * 16 * 32];
__device__ uint2 g_wf_lo[8 * 16 * 32];
// W_o fragments (fp16 hi/lo): [kstep 11][ntile 16][lane 32]
__device__ uint2 g_wfo_hi[NS_A * 16 * 32];
__device__ uint2 g_wfo_lo[NS_A * 16 * 32];
// W_i fragments (bf16 hi/lo): [kstep 3][ntile 16][lane 32]
__device__ uint2 g_wfi_hi[NS_B * 16 * 32];
__device__ uint2 g_wfi_lo[NS_B * 16 * 32];

// bf16 MMA (binput kernel)
#define MMA16816(c, a0, a1, a2, a3, b0, b1) \
    asm volatile("mma.sync.aligned.m16n8k16.row.col.f32.bf16.bf16.f32 " \
        "{%0,%1,%2,%3}, {%4,%5,%6,%7}, {%8,%9}, {%0,%1,%2,%3};" \
        : "+f"((c)[0]), "+f"((c)[1]), "+f"((c)[2]), "+f"((c)[3]) \
        : "r"(a0), "r"(a1), "r"(a2), "r"(a3), "r"(b0), "r"(b1))
// fp16 MMA (bond/atom kernels)
#define MMAF16(c, a0, a1, a2, a3, b0, b1) \
    asm volatile("mma.sync.aligned.m16n8k16.row.col.f32.f16.f16.f32 " \
        "{%0,%1,%2,%3}, {%4,%5,%6,%7}, {%8,%9}, {%0,%1,%2,%3};" \
        : "+f"((c)[0]), "+f"((c)[1]), "+f"((c)[2]), "+f"((c)[3]) \
        : "r"(a0), "r"(a1), "r"(a2), "r"(a3), "r"(b0), "r"(b1))

__device__ __forceinline__ unsigned short bf16hi(float v) {
    return __bfloat16_as_ushort(__float2bfloat16_rn(v));
}
__device__ __forceinline__ void split2(float v, unsigned short& h, unsigned short& l) {
    h = bf16hi(v);
    l = bf16hi(v - __bfloat162float(__ushort_as_bfloat16(h)));
}
// fp16 hi/lo split (22 combined mantissa bits; W effectively exact)
__device__ __forceinline__ void split2h(float v, unsigned short& h, unsigned short& l) {
    __half hh = __float2half_rn(v);
    h = __half_as_ushort(hh);
    l = __half_as_ushort(__float2half_rn(v - __half2float(hh)));
}
// accumulate 4 fp16 (as uint2) into float4
__device__ __forceinline__ void acc4h(float4& acc, uint2 v) {
    float2 f0 = __half22float2(*reinterpret_cast<__half2*>(&v.x));
    float2 f1 = __half22float2(*reinterpret_cast<__half2*>(&v.y));
    acc.x += f0.x; acc.y += f0.y; acc.z += f1.x; acc.w += f1.y;
}
__device__ __forceinline__ uint2 pack4h(float4 a) {
    __half2 h0 = __float22half2_rn(make_float2(a.x, a.y));
    __half2 h1 = __float22half2_rn(make_float2(a.z, a.w));
    return make_uint2(*reinterpret_cast<uint32_t*>(&h0),
                      *reinterpret_cast<uint32_t*>(&h1));
}

// ---------------------------------------------------------------
__global__ void tree_copy_kernel(const float* __restrict__ tree) {
    int i = blockIdx.x * blockDim.x + threadIdx.x;
    int n4 = N_MESS * H / 4;
    if (i < n4) {
        float4 v = ((const float4*)tree)[i];
        uint2 p = pack4h(v);
        ((uint2*)g_msgA)[i] = p;
        ((uint2*)g_msgB)[i] = p;
    }
}

// ---------------------------------------------------------------
// W_h [k][n] -> fp16 hi/lo B-fragments (m16n8k16):
// i = s*512 + t*32 + lane; g=lane>>2, tig=lane&3; n=t*8+g; k0=s*16+tig*2
__global__ void prep_w_kernel(const float* __restrict__ W_h) {
    int i = blockIdx.x * blockDim.x + threadIdx.x;
    if (i >= 8 * 16 * 32) return;
    int lane = i & 31, t = (i >> 5) & 15, s = i >> 9;
    int g = lane >> 2, tig = lane & 3;
    int n = t * 8 + g;
    int k0 = s * 16 + tig * 2;
    float w[4] = { W_h[(k0 + 0) * H + n], W_h[(k0 + 1) * H + n],
                   W_h[(k0 + 8) * H + n], W_h[(k0 + 9) * H + n] };
    unsigned short h[4], l[4];
#pragma unroll
    for (int j = 0; j < 4; j++) split2h(w[j], h[j], l[j]);
    g_wf_hi[i] = make_uint2((uint32_t)h[0] | ((uint32_t)h[1] << 16),
                            (uint32_t)h[2] | ((uint32_t)h[3] << 16));
    g_wf_lo[i] = make_uint2((uint32_t)l[0] | ((uint32_t)l[1] << 16),
                            (uint32_t)l[2] | ((uint32_t)l[3] << 16));
}

// W_o reordered (A col k: k<128 -> W_o row 35+k; 128..162 -> row k-128; else 0)
__device__ __forceinline__ float wo_val(const float* W_o, int k, int n) {
    if (k < 128)  return W_o[(size_t)(35 + k) * H + n];
    if (k < 163)  return W_o[(size_t)(k - 128) * H + n];
    return 0.f;
}
__global__ void prep_wo_kernel(const float* __restrict__ W_o) {
    int i = blockIdx.x * blockDim.x + threadIdx.x;
    if (i >= NS_A * 16 * 32) return;
    int lane = i & 31, t = (i >> 5) & 15, s = i >> 9;
    int g = lane >> 2, tig = lane & 3;
    int n = t * 8 + g;
    int k0 = s * 16 + tig * 2;
    float w[4] = { wo_val(W_o, k0 + 0, n), wo_val(W_o, k0 + 1, n),
                   wo_val(W_o, k0 + 8, n), wo_val(W_o, k0 + 9, n) };
    unsigned short h[4], l[4];
#pragma unroll
    for (int j = 0; j < 4; j++) split2h(w[j], h[j], l[j]);
    g_wfo_hi[i] = make_uint2((uint32_t)h[0] | ((uint32_t)h[1] << 16),
                             (uint32_t)h[2] | ((uint32_t)h[3] << 16));
    g_wfo_lo[i] = make_uint2((uint32_t)l[0] | ((uint32_t)l[1] << 16),
                             (uint32_t)l[2] | ((uint32_t)l[3] << 16));
}

// W_i [k][n] bf16 hi/lo, K padded 40->48 with zero rows
__global__ void prep_wi_kernel(const float* __restrict__ W_i) {
    int i = blockIdx.x * blockDim.x + threadIdx.x;
    if (i >= NS_B * 16 * 32) return;
    int lane = i & 31, t = (i >> 5) & 15, s = i >> 9;
    int g = lane >> 2, tig = lane & 3;
    int n = t * 8 + g;
    int k0 = s * 16 + tig * 2;
    float w[4];
    int ks[4] = { k0, k0 + 1, k0 + 8, k0 + 9 };
#pragma unroll
    for (int j = 0; j < 4; j++)
        w[j] = (ks[j] < BF) ? W_i[(size_t)ks[j] * H + n] : 0.f;
    unsigned short h[4], l[4];
#pragma unroll
    for (int j = 0; j < 4; j++) split2(w[j], h[j], l[j]);
    g_wfi_hi[i] = make_uint2((uint32_t)h[0] | ((uint32_t)h[1] << 16),
                             (uint32_t)h[2] | ((uint32_t)h[3] << 16));
    g_wfi_lo[i] = make_uint2((uint32_t)l[0] | ((uint32_t)l[1] << 16),
                             (uint32_t)l[2] | ((uint32_t)l[3] << 16));
}

// ---------------------------------------------------------------
// binput = fbonds @ W_i (fp16 out); msgA graph part = relu (fp16)   via mma
__global__ void __launch_bounds__(256, 2)
binput_mma_kernel(const float* __restrict__ fbonds) {
    extern __shared__ char smem[];
    __nv_bfloat16* Ahi = (__nv_bfloat16*)smem;            // [64][ASTRB]
    __nv_bfloat16* Alo = Ahi + 64 * ASTRB;
    uint2* WH = (uint2*)(Alo + 64 * ASTRB);               // [NS_B*512]
    uint2* WL = WH + NS_B * 512;

    int tid = threadIdx.x, warp = tid >> 5, lane = tid & 31;
    int m0 = blockIdx.x * 64;

    // stage W_i fragments: NS_B*256 uint4 per plane (bytes-derived)
    {
        const uint4* sh = (const uint4*)g_wfi_hi;
        const uint4* sl = (const uint4*)g_wfi_lo;
        uint4* dh = (uint4*)WH;
        uint4* dl = (uint4*)WL;
        for (int i = tid; i < NS_B * 256; i += 256) { dh[i] = sh[i]; dl[i] = sl[i]; }
    }

    // load fbonds rows, split hi/lo; cols [40,48) zero
    for (int i = tid; i < 64 * 48; i += 256) {
        int r = i / 48, c = i % 48;
        int m = m0 + r;
        float v = (c < BF && m < N_BONDS) ? fbonds[(size_t)m * BF + c] : 0.f;
        unsigned short h, l;
        split2(v, h, l);
        Ahi[r * ASTRB + c] = __ushort_as_bfloat16(h);
        Alo[r * ASTRB + c] = __ushort_as_bfloat16(l);
    }
    __syncthreads();

    int g = lane >> 2, tig = lane & 3;
    int r0 = (warp & 3) * 16 + g;
    int tbase = (warp >> 2) * 8;
    float c[8][4];
#pragma unroll
    for (int t = 0; t < 8; t++)
#pragma unroll
        for (int j = 0; j < 4; j++) c[t][j] = 0.f;

#pragma unroll
    for (int s = 0; s < NS_B; s++) {
        int k0 = s * 16 + tig * 2;
        uint32_t ah0 = *(const uint32_t*)&Ahi[(r0    ) * ASTRB + k0];
        uint32_t ah1 = *(const uint32_t*)&Ahi[(r0 + 8) * ASTRB + k0];
        uint32_t ah2 = *(const uint32_t*)&Ahi[(r0    ) * ASTRB + k0 + 8];
        uint32_t ah3 = *(const uint32_t*)&Ahi[(r0 + 8) * ASTRB + k0 + 8];
        uint32_t al0 = *(const uint32_t*)&Alo[(r0    ) * ASTRB + k0];
        uint32_t al1 = *(const uint32_t*)&Alo[(r0 + 8) * ASTRB + k0];
        uint32_t al2 = *(const uint32_t*)&Alo[(r0    ) * ASTRB + k0 + 8];
        uint32_t al3 = *(const uint32_t*)&Alo[(r0 + 8) * ASTRB + k0 + 8];
#pragma unroll
        for (int t = 0; t < 8; t++) {
            int fi = s * 512 + (tbase + t) * 32 + lane;
            uint2 bh = WH[fi];
            uint2 bl = WL[fi];
            MMA16816(c[t], ah0, ah1, ah2, ah3, bh.x, bh.y);
            MMA16816(c[t], ah0, ah1, ah2, ah3, bl.x, bl.y);
            MMA16816(c[t], al0, al1, al2, al3, bh.x, bh.y);
        }
    }

    __half* graphA = g_msgA + (size_t)N_MESS * H;
    int mA = m0 + r0;
    int mB = mA + 8;
    int ncol0 = (warp >> 2) * 64 + tig * 2;
#pragma unroll
    for (int t = 0; t < 8; t++) {
        int n0 = ncol0 + t * 8;
        if (mA < N_BONDS) {
            __half2 b = __float22half2_rn(make_float2(c[t][0], c[t][1]));
            *(__half2*)&g_binput[(size_t)mA * H + n0] = b;
            __half2 r = __float22half2_rn(
                make_float2(fmaxf(c[t][0], 0.f), fmaxf(c[t][1], 0.f)));
            *(__half2*)&graphA[(size_t)mA * H + n0] = r;
        }
        if (mB < N_BONDS) {
            __half2 b = __float22half2_rn(make_float2(c[t][2], c[t][3]));
            *(__half2*)&g_binput[(size_t)mB * H + n0] = b;
            __half2 r = __float22half2_rn(
                make_float2(fmaxf(c[t][2], 0.f), fmaxf(c[t][3], 0.f)));
            *(__half2*)&graphA[(size_t)mB * H + n0] = r;
        }
    }
}

// ---------------------------------------------------------------
// bond iter: dst = relu(binput + gathersum(src)@W_h)
// fp16 2-term scheme: A = fp16(sum), W = fp16 hi + fp16 lo (W exact to 2e-7).
// 2 MMAs per fragment pair (was 3); single A plane in smem.
__global__ void __launch_bounds__(512, 2)
bond_mma_kernel(const __half* __restrict__ src_msg,
                __half* __restrict__ dst_graph,
                const int* __restrict__ bgraph) {
    extern __shared__ char smem[];
    __half* Ah = (__half*)smem;                           // [BMT][ASTR]
    uint2* WH = (uint2*)(Ah + BMT * ASTR);                // [4096]
    uint2* WL = WH + 4096;

    int tid = threadIdx.x, warp = tid >> 5, lane = tid & 31;
    int m0 = blockIdx.x * BMT;

    // stage W fragments (64 KB = 2 x 2048 uint4)
    {
        const uint4* sh = (const uint4*)g_wf_hi;
        const uint4* sl = (const uint4*)g_wf_lo;
        uint4* dh = (uint4*)WH;
        uint4* dl = (uint4*)WL;
        for (int i = tid; i < 2048; i += 512) { dh[i] = sh[i]; dl[i] = sl[i]; }
    }

    // gather: warp -> 4 rows, lane -> cols [4l, 4l+4) (8B fp16 per lane)
#pragma unroll
    for (int i = 0; i < 4; i++) {
        int r = warp * 4 + i;
        int m = m0 + r;
        float4 acc = make_float4(0.f, 0.f, 0.f, 0.f);
        if (m < N_BONDS) {
            const int* bg = &bgraph[m * NBR];
#pragma unroll
            for (int nb = 0; nb < NBR; nb++) {
                int idx = __ldg(&bg[nb]);
                uint2 v = *(const uint2*)&src_msg[(size_t)idx * H + lane * 4];
                acc4h(acc, v);
            }
        }
        *(uint2*)&Ah[r * ASTR + lane * 4] = pack4h(acc);
    }
    __syncthreads();

    // MMA: warp (w&3) -> 16-row group, (w>>2) -> 32-col group
    int g = lane >> 2, tig = lane & 3;
    int r0 = (warp & 3) * 16 + g;
    int tbase = (warp >> 2) * 4;
    float c[4][4];
#pragma unroll
    for (int t = 0; t < 4; t++)
#pragma unroll
        for (int j = 0; j < 4; j++) c[t][j] = 0.f;

#pragma unroll
    for (int s = 0; s < 8; s++) {
        int k0 = s * 16 + tig * 2;
        uint32_t a0 = *(const uint32_t*)&Ah[(r0    ) * ASTR + k0];
        uint32_t a1 = *(const uint32_t*)&Ah[(r0 + 8) * ASTR + k0];
        uint32_t a2 = *(const uint32_t*)&Ah[(r0    ) * ASTR + k0 + 8];
        uint32_t a3 = *(const uint32_t*)&Ah[(r0 + 8) * ASTR + k0 + 8];
#pragma unroll
        for (int t = 0; t < 4; t++) {
            uint2 bh = WH[s * 512 + (tbase + t) * 32 + lane];
            uint2 bl = WL[s * 512 + (tbase + t) * 32 + lane];
            MMAF16(c[t], a0, a1, a2, a3, bh.x, bh.y);
            MMAF16(c[t], a0, a1, a2, a3, bl.x, bl.y);
        }
    }

    // epilogue: +binput (fp16), relu, store fp16
    int mA = m0 + r0;
    int mB = mA + 8;
    int ncol0 = (warp >> 2) * 32 + tig * 2;
#pragma unroll
    for (int t = 0; t < 4; t++) {
        int n0 = ncol0 + t * 8;
        if (mA < N_BONDS) {
            float2 bi = __half22float2(
                *(const __half2*)&g_binput[(size_t)mA * H + n0]);
            __half2 o = __float22half2_rn(
                make_float2(fmaxf(bi.x + c[t][0], 0.f),
                            fmaxf(bi.y + c[t][1], 0.f)));
            *(__half2*)&dst_graph[(size_t)mA * H + n0] = o;
        }
        if (mB < N_BONDS) {
            float2 bi = __half22float2(
                *(const __half2*)&g_binput[(size_t)mB * H + n0]);
            __half2 o = __float22half2_rn(
                make_float2(fmaxf(bi.x + c[t][2], 0.f),
                            fmaxf(bi.y + c[t][3], 0.f)));
            *(__half2*)&dst_graph[(size_t)mB * H + n0] = o;
        }
    }
}

// ---------------------------------------------------------------
// atom: g_atomh = relu([nei(128)|fatoms(35)|pad] @ Wo + b_o)
// fp16 2-term: A fp16 single plane; Wo hi in smem, Wo lo via __ldg.
__global__ void __launch_bounds__(256, 2)
atom_mma_kernel(const __half* __restrict__ src_msg,
                const int* __restrict__ agraph,
                const float* __restrict__ fatoms,
                const float* __restrict__ b_o) {
    extern __shared__ char smem[];
    __half* Ah = (__half*)smem;                           // [64][ASTRA]
    uint2* WH = (uint2*)(Ah + 64 * ASTRA);                // [NS_A*512]

    int tid = threadIdx.x, warp = tid >> 5, lane = tid & 31;
    int m0 = blockIdx.x * 64;

    // stage Wo hi fragments: NS_A*256 uint4 (bytes-derived)
    {
        const uint4* sh = (const uint4*)g_wfo_hi;
        uint4* dh = (uint4*)WH;
        for (int i = tid; i < NS_A * 256; i += 256) dh[i] = sh[i];
    }

    // nei gather into cols [0,128)  (fp16 messages)
#pragma unroll
    for (int i = 0; i < 8; i++) {
        int r = warp * 8 + i;
        int m = m0 + r;
        float4 acc = make_float4(0.f, 0.f, 0.f, 0.f);
        if (m < N_ATOMS) {
            const int* ag = &agraph[m * NBR];
#pragma unroll
            for (int nb = 0; nb < NBR; nb++) {
                int idx = __ldg(&ag[nb]);
                uint2 v = *(const uint2*)&src_msg[(size_t)idx * H + lane * 4];
                acc4h(acc, v);
            }
        }
        *(uint2*)&Ah[r * ASTRA + lane * 4] = pack4h(acc);
    }
    // fatoms into cols [128,163), zero pad [163,176)
    for (int i = tid; i < 64 * 48; i += 256) {
        int r = i / 48, cc = 128 + (i % 48);
        int m = m0 + r;
        float v = (cc < 163 && m < N_ATOMS)
                  ? fatoms[(size_t)m * AF + (cc - 128)] : 0.f;
        Ah[r * ASTRA + cc] = __float2half_rn(v);
    }
    __syncthreads();

    int g = lane >> 2, tig = lane & 3;
    int r0 = (warp & 3) * 16 + g;
    int tbase = (warp >> 2) * 8;
    float c[8][4];
#pragma unroll
    for (int t = 0; t < 8; t++)
#pragma unroll
        for (int j = 0; j < 4; j++) c[t][j] = 0.f;

#pragma unroll
    for (int s = 0; s < NS_A; s++) {
        int k0 = s * 16 + tig * 2;
        uint32_t a0 = *(const uint32_t*)&Ah[(r0    ) * ASTRA + k0];
        uint32_t a1 = *(const uint32_t*)&Ah[(r0 + 8) * ASTRA + k0];
        uint32_t a2 = *(const uint32_t*)&Ah[(r0    ) * ASTRA + k0 + 8];
        uint32_t a3 = *(const uint32_t*)&Ah[(r0 + 8) * ASTRA + k0 + 8];
#pragma unroll
        for (int t = 0; t < 8; t++) {
            int fi = s * 512 + (tbase + t) * 32 + lane;
            uint2 bh = WH[fi];
            uint2 bl = __ldg(&g_wfo_lo[fi]);
            MMAF16(c[t], a0, a1, a2, a3, bh.x, bh.y);
            MMAF16(c[t], a0, a1, a2, a3, bl.x, bl.y);
        }
    }

    int mA = m0 + r0;
    int mB = mA + 8;
    int ncol0 = (warp >> 2) * 64 + tig * 2;
#pragma unroll
    for (int t = 0; t < 8; t++) {
        int n0 = ncol0 + t * 8;
        float2 bo = *(const float2*)&b_o[n0];
        if (mA < N_ATOMS) {
            float2 o = make_float2(fmaxf(bo.x + c[t][0], 0.f),
                                   fmaxf(bo.y + c[t][1], 0.f));
            *(float2*)&g_atomh[(size_t)mA * H + n0] = o;
        }
        if (mB < N_ATOMS) {
            float2 o = make_float2(fmaxf(bo.x + c[t][2], 0.f),
                                   fmaxf(bo.y + c[t][3], 0.f));
            *(float2*)&g_atomh[(size_t)mB * H + n0] = o;
        }
    }
}

// ---------------------------------------------------------------
__device__ __forceinline__ int lowerb(const int* __restrict__ a, int n, int key) {
    int lo = 0, hi = n;
    while (lo < hi) {
        int mid = (lo + hi) >> 1;
        if (a[mid] < key) lo = mid + 1; else hi = mid;
    }
    return lo;
}

__global__ void pool_kernel(const int* __restrict__ mol_ids,
                            float* __restrict__ out) {
    int mol = blockIdx.x;
    int tid = threadIdx.x;
    int lo = lowerb(mol_ids, N_ATOMS, mol);
    int hi = lowerb(mol_ids, N_ATOMS, mol + 1);
    float s = 0.f;
    for (int a = lo; a < hi; a++)
        s += g_atomh[(size_t)a * H + tid];
    int cnt = hi - lo;
    out[(size_t)mol * H + tid] = cnt ? s / (float)cnt : 0.f;
}

// ---------------------------------------------------------------
extern "C" void kernel_launch(void* const* d_in, const int* in_sizes, int n_in,
                              void* d_out, int out_size) {
    const float *fatoms = nullptr, *fbonds = nullptr, *tree = nullptr;
    const float *W_i = nullptr, *W_h = nullptr, *W_o = nullptr, *b_o = nullptr;
    const int *agraph = nullptr, *bgraph = nullptr, *mol_ids = nullptr;
    for (int i = 0; i < n_in; i++) {
        switch (in_sizes[i]) {
            case 3500000: fatoms  = (const float*)d_in[i]; break;   // 100000*35
            case 8800000: fbonds  = (const float*)d_in[i]; break;   // 220000*40
            case 2560000: tree    = (const float*)d_in[i]; break;   // 20000*128
            case 1000000: agraph  = (const int*)d_in[i];   break;   // 100000*10
            case 2200000: bgraph  = (const int*)d_in[i];   break;   // 220000*10
            case 100000:  mol_ids = (const int*)d_in[i];   break;
            case 5120:    W_i     = (const float*)d_in[i]; break;   // 40*128
            case 16384:   W_h     = (const float*)d_in[i]; break;   // 128*128
            case 20864:   W_o     = (const float*)d_in[i]; break;   // 163*128
            case 128:     b_o     = (const float*)d_in[i]; break;
        }
    }

    const int BOND_SMEM = BMT * ASTR * 2 + 4096 * 8 * 2;       // 17408+65536=82944
    const int ATOM_SMEM = 64 * ASTRA * 2 + NS_A * 512 * 8;     // 23552+45056=68608
    const int BINM_SMEM = 64 * ASTRB * 2 * 2 + NS_B * 512 * 8 * 2; // 38912
    cudaFuncSetAttribute(bond_mma_kernel,
                         cudaFuncAttributeMaxDynamicSharedMemorySize, BOND_SMEM);
    cudaFuncSetAttribute(atom_mma_kernel,
                         cudaFuncAttributeMaxDynamicSharedMemorySize, ATOM_SMEM);

    __half *msgA, *msgB;
    cudaGetSymbolAddress((void**)&msgA, g_msgA);
    cudaGetSymbolAddress((void**)&msgB, g_msgB);

    int tc_blocks = (N_MESS * H / 4 + 255) / 256;
    tree_copy_kernel<<<tc_blocks, 256>>>(tree);
    prep_w_kernel<<<(8 * 16 * 32 + 255) / 256, 256>>>(W_h);
    prep_wo_kernel<<<(NS_A * 16 * 32 + 255) / 256, 256>>>(W_o);
    prep_wi_kernel<<<(NS_B * 16 * 32 + 255) / 256, 256>>>(W_i);

    int grid_bin = (N_BONDS + 63) / 64;   // 3438
    binput_mma_kernel<<<grid_bin, 256, BINM_SMEM>>>(fbonds);

    __half* src = msgA;
    __half* dst = msgB;
    int grid_mma = (N_BONDS + BMT - 1) / BMT;   // 3438
    for (int it = 0; it < 5; it++) {            // DEPTH-1
        bond_mma_kernel<<<grid_mma, 512, BOND_SMEM>>>(
            src, dst + (size_t)N_MESS * H, bgraph);
        __half* t = src; src = dst; dst = t;
    }

    int grid_a = (N_ATOMS + 63) / 64;           // 1563
    atom_mma_kernel<<<grid_a, 256, ATOM_SMEM>>>(src, agraph, fatoms, b_o);

    pool_kernel<<<N_MOLS, H>>>(mol_ids, (float*)d_out);
}

// round 16
// speedup vs baseline: 2.1595x; 1.1102x over previous
#include <cuda_runtime.h>
#include <cuda_bf16.h>
#include <cuda_fp16.h>
#include <cstdint>

#define H       128
#define NBR     10
#define AF      35
#define BF      40            // ATOM_FDIM + BOND_FDIM
#define N_ATOMS 100000
#define N_BONDS 220000
#define N_MESS  20000
#define N_MOLS  2000
#define MSG_ROWS (N_MESS + N_BONDS)

// bond mma kernel tiling
#define BMT     64            // rows per block
#define ASTR    136           // A row stride (fp16), conflict-free fragments
// atom mma kernel tiling
#define ASTRA   184           // A row stride (fp16)
#define NS_A    11            // k-steps for atom
// binput mma kernel tiling (bf16 3-term, unchanged)
#define ASTRB   56            // A row stride (bf16) for K=48
#define NS_B    3             // k-steps for binput (K padded 40->48)

// ---- scratch (device globals: allocation-free kernel_launch) ----
__device__ __half g_msgA[(size_t)MSG_ROWS * H];
__device__ __half g_msgB[(size_t)MSG_ROWS * H];
__device__ __half g_binput[(size_t)N_BONDS * H];
__device__ float g_atomh[(size_t)N_ATOMS * H];
// W_h fragments (single fp16): [kstep 8][ntile 16][lane 32] uint2
__device__ uint2 g_wf_hi[8 * 16 * 32];
// W_o fragments (single fp16): [kstep 11][ntile 16][lane 32]
__device__ uint2 g_wfo_hi[NS_A * 16 * 32];
// W_i fragments (bf16 hi/lo): [kstep 3][ntile 16][lane 32]
__device__ uint2 g_wfi_hi[NS_B * 16 * 32];
__device__ uint2 g_wfi_lo[NS_B * 16 * 32];

// bf16 MMA (binput kernel)
#define MMA16816(c, a0, a1, a2, a3, b0, b1) \
    asm volatile("mma.sync.aligned.m16n8k16.row.col.f32.bf16.bf16.f32 " \
        "{%0,%1,%2,%3}, {%4,%5,%6,%7}, {%8,%9}, {%0,%1,%2,%3};" \
        : "+f"((c)[0]), "+f"((c)[1]), "+f"((c)[2]), "+f"((c)[3]) \
        : "r"(a0), "r"(a1), "r"(a2), "r"(a3), "r"(b0), "r"(b1))
// fp16 MMA (bond/atom kernels)
#define MMAF16(c, a0, a1, a2, a3, b0, b1) \
    asm volatile("mma.sync.aligned.m16n8k16.row.col.f32.f16.f16.f32 " \
        "{%0,%1,%2,%3}, {%4,%5,%6,%7}, {%8,%9}, {%0,%1,%2,%3};" \
        : "+f"((c)[0]), "+f"((c)[1]), "+f"((c)[2]), "+f"((c)[3]) \
        : "r"(a0), "r"(a1), "r"(a2), "r"(a3), "r"(b0), "r"(b1))

__device__ __forceinline__ unsigned short bf16hi(float v) {
    return __bfloat16_as_ushort(__float2bfloat16_rn(v));
}
__device__ __forceinline__ void split2(float v, unsigned short& h, unsigned short& l) {
    h = bf16hi(v);
    l = bf16hi(v - __bfloat162float(__ushort_as_bfloat16(h)));
}
// accumulate 4 fp16 (as uint2) into float4
__device__ __forceinline__ void acc4h(float4& acc, uint2 v) {
    float2 f0 = __half22float2(*reinterpret_cast<__half2*>(&v.x));
    float2 f1 = __half22float2(*reinterpret_cast<__half2*>(&v.y));
    acc.x += f0.x; acc.y += f0.y; acc.z += f1.x; acc.w += f1.y;
}
__device__ __forceinline__ uint2 pack4h(float4 a) {
    __half2 h0 = __float22half2_rn(make_float2(a.x, a.y));
    __half2 h1 = __float22half2_rn(make_float2(a.z, a.w));
    return make_uint2(*reinterpret_cast<uint32_t*>(&h0),
                      *reinterpret_cast<uint32_t*>(&h1));
}

// ---------------------------------------------------------------
__global__ void tree_copy_kernel(const float* __restrict__ tree) {
    int i = blockIdx.x * blockDim.x + threadIdx.x;
    int n4 = N_MESS * H / 4;
    if (i < n4) {
        float4 v = ((const float4*)tree)[i];
        uint2 p = pack4h(v);
        ((uint2*)g_msgA)[i] = p;
        ((uint2*)g_msgB)[i] = p;
    }
}

// ---------------------------------------------------------------
// W_h [k][n] -> single fp16 B-fragments (m16n8k16):
// i = s*512 + t*32 + lane; g=lane>>2, tig=lane&3; n=t*8+g; k0=s*16+tig*2
__global__ void prep_w_kernel(const float* __restrict__ W_h) {
    int i = blockIdx.x * blockDim.x + threadIdx.x;
    if (i >= 8 * 16 * 32) return;
    int lane = i & 31, t = (i >> 5) & 15, s = i >> 9;
    int g = lane >> 2, tig = lane & 3;
    int n = t * 8 + g;
    int k0 = s * 16 + tig * 2;
    unsigned short h[4] = {
        __half_as_ushort(__float2half_rn(W_h[(k0 + 0) * H + n])),
        __half_as_ushort(__float2half_rn(W_h[(k0 + 1) * H + n])),
        __half_as_ushort(__float2half_rn(W_h[(k0 + 8) * H + n])),
        __half_as_ushort(__float2half_rn(W_h[(k0 + 9) * H + n])) };
    g_wf_hi[i] = make_uint2((uint32_t)h[0] | ((uint32_t)h[1] << 16),
                            (uint32_t)h[2] | ((uint32_t)h[3] << 16));
}

// W_o reordered (A col k: k<128 -> W_o row 35+k; 128..162 -> row k-128; else 0)
__device__ __forceinline__ float wo_val(const float* W_o, int k, int n) {
    if (k < 128)  return W_o[(size_t)(35 + k) * H + n];
    if (k < 163)  return W_o[(size_t)(k - 128) * H + n];
    return 0.f;
}
__global__ void prep_wo_kernel(const float* __restrict__ W_o) {
    int i = blockIdx.x * blockDim.x + threadIdx.x;
    if (i >= NS_A * 16 * 32) return;
    int lane = i & 31, t = (i >> 5) & 15, s = i >> 9;
    int g = lane >> 2, tig = lane & 3;
    int n = t * 8 + g;
    int k0 = s * 16 + tig * 2;
    unsigned short h[4] = {
        __half_as_ushort(__float2half_rn(wo_val(W_o, k0 + 0, n))),
        __half_as_ushort(__float2half_rn(wo_val(W_o, k0 + 1, n))),
        __half_as_ushort(__float2half_rn(wo_val(W_o, k0 + 8, n))),
        __half_as_ushort(__float2half_rn(wo_val(W_o, k0 + 9, n))) };
    g_wfo_hi[i] = make_uint2((uint32_t)h[0] | ((uint32_t)h[1] << 16),
                             (uint32_t)h[2] | ((uint32_t)h[3] << 16));
}

// W_i [k][n] bf16 hi/lo, K padded 40->48 with zero rows
__global__ void prep_wi_kernel(const float* __restrict__ W_i) {
    int i = blockIdx.x * blockDim.x + threadIdx.x;
    if (i >= NS_B * 16 * 32) return;
    int lane = i & 31, t = (i >> 5) & 15, s = i >> 9;
    int g = lane >> 2, tig = lane & 3;
    int n = t * 8 + g;
    int k0 = s * 16 + tig * 2;
    float w[4];
    int ks[4] = { k0, k0 + 1, k0 + 8, k0 + 9 };
#pragma unroll
    for (int j = 0; j < 4; j++)
        w[j] = (ks[j] < BF) ? W_i[(size_t)ks[j] * H + n] : 0.f;
    unsigned short h[4], l[4];
#pragma unroll
    for (int j = 0; j < 4; j++) split2(w[j], h[j], l[j]);
    g_wfi_hi[i] = make_uint2((uint32_t)h[0] | ((uint32_t)h[1] << 16),
                             (uint32_t)h[2] | ((uint32_t)h[3] << 16));
    g_wfi_lo[i] = make_uint2((uint32_t)l[0] | ((uint32_t)l[1] << 16),
                             (uint32_t)l[2] | ((uint32_t)l[3] << 16));
}

// ---------------------------------------------------------------
// binput = fbonds @ W_i (fp16 out); msgA graph part = relu (fp16)   via mma
__global__ void __launch_bounds__(256, 2)
binput_mma_kernel(const float* __restrict__ fbonds) {
    extern __shared__ char smem[];
    __nv_bfloat16* Ahi = (__nv_bfloat16*)smem;            // [64][ASTRB]
    __nv_bfloat16* Alo = Ahi + 64 * ASTRB;
    uint2* WH = (uint2*)(Alo + 64 * ASTRB);               // [NS_B*512]
    uint2* WL = WH + NS_B * 512;

    int tid = threadIdx.x, warp = tid >> 5, lane = tid & 31;
    int m0 = blockIdx.x * 64;

    // stage W_i fragments: NS_B*256 uint4 per plane (bytes-derived)
    {
        const uint4* sh = (const uint4*)g_wfi_hi;
        const uint4* sl = (const uint4*)g_wfi_lo;
        uint4* dh = (uint4*)WH;
        uint4* dl = (uint4*)WL;
        for (int i = tid; i < NS_B * 256; i += 256) { dh[i] = sh[i]; dl[i] = sl[i]; }
    }

    // load fbonds rows, split hi/lo; cols [40,48) zero
    for (int i = tid; i < 64 * 48; i += 256) {
        int r = i / 48, c = i % 48;
        int m = m0 + r;
        float v = (c < BF && m < N_BONDS) ? fbonds[(size_t)m * BF + c] : 0.f;
        unsigned short h, l;
        split2(v, h, l);
        Ahi[r * ASTRB + c] = __ushort_as_bfloat16(h);
        Alo[r * ASTRB + c] = __ushort_as_bfloat16(l);
    }
    __syncthreads();

    int g = lane >> 2, tig = lane & 3;
    int r0 = (warp & 3) * 16 + g;
    int tbase = (warp >> 2) * 8;
    float c[8][4];
#pragma unroll
    for (int t = 0; t < 8; t++)
#pragma unroll
        for (int j = 0; j < 4; j++) c[t][j] = 0.f;

#pragma unroll
    for (int s = 0; s < NS_B; s++) {
        int k0 = s * 16 + tig * 2;
        uint32_t ah0 = *(const uint32_t*)&Ahi[(r0    ) * ASTRB + k0];
        uint32_t ah1 = *(const uint32_t*)&Ahi[(r0 + 8) * ASTRB + k0];
        uint32_t ah2 = *(const uint32_t*)&Ahi[(r0    ) * ASTRB + k0 + 8];
        uint32_t ah3 = *(const uint32_t*)&Ahi[(r0 + 8) * ASTRB + k0 + 8];
        uint32_t al0 = *(const uint32_t*)&Alo[(r0    ) * ASTRB + k0];
        uint32_t al1 = *(const uint32_t*)&Alo[(r0 + 8) * ASTRB + k0];
        uint32_t al2 = *(const uint32_t*)&Alo[(r0    ) * ASTRB + k0 + 8];
        uint32_t al3 = *(const uint32_t*)&Alo[(r0 + 8) * ASTRB + k0 + 8];
#pragma unroll
        for (int t = 0; t < 8; t++) {
            int fi = s * 512 + (tbase + t) * 32 + lane;
            uint2 bh = WH[fi];
            uint2 bl = WL[fi];
            MMA16816(c[t], ah0, ah1, ah2, ah3, bh.x, bh.y);
            MMA16816(c[t], ah0, ah1, ah2, ah3, bl.x, bl.y);
            MMA16816(c[t], al0, al1, al2, al3, bh.x, bh.y);
        }
    }

    __half* graphA = g_msgA + (size_t)N_MESS * H;
    int mA = m0 + r0;
    int mB = mA + 8;
    int ncol0 = (warp >> 2) * 64 + tig * 2;
#pragma unroll
    for (int t = 0; t < 8; t++) {
        int n0 = ncol0 + t * 8;
        if (mA < N_BONDS) {
            __half2 b = __float22half2_rn(make_float2(c[t][0], c[t][1]));
            *(__half2*)&g_binput[(size_t)mA * H + n0] = b;
            __half2 r = __float22half2_rn(
                make_float2(fmaxf(c[t][0], 0.f), fmaxf(c[t][1], 0.f)));
            *(__half2*)&graphA[(size_t)mA * H + n0] = r;
        }
        if (mB < N_BONDS) {
            __half2 b = __float22half2_rn(make_float2(c[t][2], c[t][3]));
            *(__half2*)&g_binput[(size_t)mB * H + n0] = b;
            __half2 r = __float22half2_rn(
                make_float2(fmaxf(c[t][2], 0.f), fmaxf(c[t][3], 0.f)));
            *(__half2*)&graphA[(size_t)mB * H + n0] = r;
        }
    }
}

// ---------------------------------------------------------------
// bond iter: dst = relu(binput + gathersum(src)@W_h)
// single-fp16 A and W: 1 MMA per fragment pair. W staging 32 KB.
__global__ void __launch_bounds__(512, 2)
bond_mma_kernel(const __half* __restrict__ src_msg,
                __half* __restrict__ dst_graph,
                const int* __restrict__ bgraph) {
    extern __shared__ char smem[];
    __half* Ah = (__half*)smem;                           // [BMT][ASTR]
    uint2* WH = (uint2*)(Ah + BMT * ASTR);                // [4096]

    int tid = threadIdx.x, warp = tid >> 5, lane = tid & 31;
    int m0 = blockIdx.x * BMT;

    // stage W fragments (32 KB = 2048 uint4)
    {
        const uint4* sh = (const uint4*)g_wf_hi;
        uint4* dh = (uint4*)WH;
        for (int i = tid; i < 2048; i += 512) dh[i] = sh[i];
    }

    // gather: warp -> 4 rows, lane -> cols [4l, 4l+4) (8B fp16 per lane)
#pragma unroll
    for (int i = 0; i < 4; i++) {
        int r = warp * 4 + i;
        int m = m0 + r;
        float4 acc = make_float4(0.f, 0.f, 0.f, 0.f);
        if (m < N_BONDS) {
            const int* bg = &bgraph[m * NBR];
#pragma unroll
            for (int nb = 0; nb < NBR; nb++) {
                int idx = __ldg(&bg[nb]);
                uint2 v = *(const uint2*)&src_msg[(size_t)idx * H + lane * 4];
                acc4h(acc, v);
            }
        }
        *(uint2*)&Ah[r * ASTR + lane * 4] = pack4h(acc);
    }
    __syncthreads();

    // MMA: warp (w&3) -> 16-row group, (w>>2) -> 32-col group
    int g = lane >> 2, tig = lane & 3;
    int r0 = (warp & 3) * 16 + g;
    int tbase = (warp >> 2) * 4;
    float c[4][4];
#pragma unroll
    for (int t = 0; t < 4; t++)
#pragma unroll
        for (int j = 0; j < 4; j++) c[t][j] = 0.f;

#pragma unroll
    for (int s = 0; s < 8; s++) {
        int k0 = s * 16 + tig * 2;
        uint32_t a0 = *(const uint32_t*)&Ah[(r0    ) * ASTR + k0];
        uint32_t a1 = *(const uint32_t*)&Ah[(r0 + 8) * ASTR + k0];
        uint32_t a2 = *(const uint32_t*)&Ah[(r0    ) * ASTR + k0 + 8];
        uint32_t a3 = *(const uint32_t*)&Ah[(r0 + 8) * ASTR + k0 + 8];
#pragma unroll
        for (int t = 0; t < 4; t++) {
            uint2 bh = WH[s * 512 + (tbase + t) * 32 + lane];
            MMAF16(c[t], a0, a1, a2, a3, bh.x, bh.y);
        }
    }

    // epilogue: +binput (fp16), relu, store fp16
    int mA = m0 + r0;
    int mB = mA + 8;
    int ncol0 = (warp >> 2) * 32 + tig * 2;
#pragma unroll
    for (int t = 0; t < 4; t++) {
        int n0 = ncol0 + t * 8;
        if (mA < N_BONDS) {
            float2 bi = __half22float2(
                *(const __half2*)&g_binput[(size_t)mA * H + n0]);
            __half2 o = __float22half2_rn(
                make_float2(fmaxf(bi.x + c[t][0], 0.f),
                            fmaxf(bi.y + c[t][1], 0.f)));
            *(__half2*)&dst_graph[(size_t)mA * H + n0] = o;
        }
        if (mB < N_BONDS) {
            float2 bi = __half22float2(
                *(const __half2*)&g_binput[(size_t)mB * H + n0]);
            __half2 o = __float22half2_rn(
                make_float2(fmaxf(bi.x + c[t][2], 0.f),
                            fmaxf(bi.y + c[t][3], 0.f)));
            *(__half2*)&dst_graph[(size_t)mB * H + n0] = o;
        }
    }
}

// ---------------------------------------------------------------
// atom: g_atomh = relu([nei(128)|fatoms(35)|pad] @ Wo + b_o)
// single-fp16 A and W: 1 MMA per fragment.
__global__ void __launch_bounds__(256, 2)
atom_mma_kernel(const __half* __restrict__ src_msg,
                const int* __restrict__ agraph,
                const float* __restrict__ fatoms,
                const float* __restrict__ b_o) {
    extern __shared__ char smem[];
    __half* Ah = (__half*)smem;                           // [64][ASTRA]
    uint2* WH = (uint2*)(Ah + 64 * ASTRA);                // [NS_A*512]

    int tid = threadIdx.x, warp = tid >> 5, lane = tid & 31;
    int m0 = blockIdx.x * 64;

    // stage Wo fragments: NS_A*256 uint4 (bytes-derived)
    {
        const uint4* sh = (const uint4*)g_wfo_hi;
        uint4* dh = (uint4*)WH;
        for (int i = tid; i < NS_A * 256; i += 256) dh[i] = sh[i];
    }

    // nei gather into cols [0,128)  (fp16 messages)
#pragma unroll
    for (int i = 0; i < 8; i++) {
        int r = warp * 8 + i;
        int m = m0 + r;
        float4 acc = make_float4(0.f, 0.f, 0.f, 0.f);
        if (m < N_ATOMS) {
            const int* ag = &agraph[m * NBR];
#pragma unroll
            for (int nb = 0; nb < NBR; nb++) {
                int idx = __ldg(&ag[nb]);
                uint2 v = *(const uint2*)&src_msg[(size_t)idx * H + lane * 4];
                acc4h(acc, v);
            }
        }
        *(uint2*)&Ah[r * ASTRA + lane * 4] = pack4h(acc);
    }
    // fatoms into cols [128,163), zero pad [163,176)
    for (int i = tid; i < 64 * 48; i += 256) {
        int r = i / 48, cc = 128 + (i % 48);
        int m = m0 + r;
        float v = (cc < 163 && m < N_ATOMS)
                  ? fatoms[(size_t)m * AF + (cc - 128)] : 0.f;
        Ah[r * ASTRA + cc] = __float2half_rn(v);
    }
    __syncthreads();

    int g = lane >> 2, tig = lane & 3;
    int r0 = (warp & 3) * 16 + g;
    int tbase = (warp >> 2) * 8;
    float c[8][4];
#pragma unroll
    for (int t = 0; t < 8; t++)
#pragma unroll
        for (int j = 0; j < 4; j++) c[t][j] = 0.f;

#pragma unroll
    for (int s = 0; s < NS_A; s++) {
        int k0 = s * 16 + tig * 2;
        uint32_t a0 = *(const uint32_t*)&Ah[(r0    ) * ASTRA + k0];
        uint32_t a1 = *(const uint32_t*)&Ah[(r0 + 8) * ASTRA + k0];
        uint32_t a2 = *(const uint32_t*)&Ah[(r0    ) * ASTRA + k0 + 8];
        uint32_t a3 = *(const uint32_t*)&Ah[(r0 + 8) * ASTRA + k0 + 8];
#pragma unroll
        for (int t = 0; t < 8; t++) {
            int fi = s * 512 + (tbase + t) * 32 + lane;
            uint2 bh = WH[fi];
            MMAF16(c[t], a0, a1, a2, a3, bh.x, bh.y);
        }
    }

    int mA = m0 + r0;
    int mB = mA + 8;
    int ncol0 = (warp >> 2) * 64 + tig * 2;
#pragma unroll
    for (int t = 0; t < 8; t++) {
        int n0 = ncol0 + t * 8;
        float2 bo = *(const float2*)&b_o[n0];
        if (mA < N_ATOMS) {
            float2 o = make_float2(fmaxf(bo.x + c[t][0], 0.f),
                                   fmaxf(bo.y + c[t][1], 0.f));
            *(float2*)&g_atomh[(size_t)mA * H + n0] = o;
        }
        if (mB < N_ATOMS) {
            float2 o = make_float2(fmaxf(bo.x + c[t][2], 0.f),
                                   fmaxf(bo.y + c[t][3], 0.f));
            *(float2*)&g_atomh[(size_t)mB * H + n0] = o;
        }
    }
}

// ---------------------------------------------------------------
__device__ __forceinline__ int lowerb(const int* __restrict__ a, int n, int key) {
    int lo = 0, hi = n;
    while (lo < hi) {
        int mid = (lo + hi) >> 1;
        if (a[mid] < key) lo = mid + 1; else hi = mid;
    }
    return lo;
}

__global__ void pool_kernel(const int* __restrict__ mol_ids,
                            float* __restrict__ out) {
    int mol = blockIdx.x;
    int tid = threadIdx.x;
    int lo = lowerb(mol_ids, N_ATOMS, mol);
    int hi = lowerb(mol_ids, N_ATOMS, mol + 1);
    float s = 0.f;
    for (int a = lo; a < hi; a++)
        s += g_atomh[(size_t)a * H + tid];
    int cnt = hi - lo;
    out[(size_t)mol * H + tid] = cnt ? s / (float)cnt : 0.f;
}

// ---------------------------------------------------------------
extern "C" void kernel_launch(void* const* d_in, const int* in_sizes, int n_in,
                              void* d_out, int out_size) {
    const float *fatoms = nullptr, *fbonds = nullptr, *tree = nullptr;
    const float *W_i = nullptr, *W_h = nullptr, *W_o = nullptr, *b_o = nullptr;
    const int *agraph = nullptr, *bgraph = nullptr, *mol_ids = nullptr;
    for (int i = 0; i < n_in; i++) {
        switch (in_sizes[i]) {
            case 3500000: fatoms  = (const float*)d_in[i]; break;   // 100000*35
            case 8800000: fbonds  = (const float*)d_in[i]; break;   // 220000*40
            case 2560000: tree    = (const float*)d_in[i]; break;   // 20000*128
            case 1000000: agraph  = (const int*)d_in[i];   break;   // 100000*10
            case 2200000: bgraph  = (const int*)d_in[i];   break;   // 220000*10
            case 100000:  mol_ids = (const int*)d_in[i];   break;
            case 5120:    W_i     = (const float*)d_in[i]; break;   // 40*128
            case 16384:   W_h     = (const float*)d_in[i]; break;   // 128*128
            case 20864:   W_o     = (const float*)d_in[i]; break;   // 163*128
            case 128:     b_o     = (const float*)d_in[i]; break;
        }
    }

    const int BOND_SMEM = BMT * ASTR * 2 + 4096 * 8;           // 17408+32768=50176
    const int ATOM_SMEM = 64 * ASTRA * 2 + NS_A * 512 * 8;     // 23552+45056=68608
    const int BINM_SMEM = 64 * ASTRB * 2 * 2 + NS_B * 512 * 8 * 2; // 38912
    cudaFuncSetAttribute(bond_mma_kernel,
                         cudaFuncAttributeMaxDynamicSharedMemorySize, BOND_SMEM);
    cudaFuncSetAttribute(atom_mma_kernel,
                         cudaFuncAttributeMaxDynamicSharedMemorySize, ATOM_SMEM);

    __half *msgA, *msgB;
    cudaGetSymbolAddress((void**)&msgA, g_msgA);
    cudaGetSymbolAddress((void**)&msgB, g_msgB);

    int tc_blocks = (N_MESS * H / 4 + 255) / 256;
    tree_copy_kernel<<<tc_blocks, 256>>>(tree);
    prep_w_kernel<<<(8 * 16 * 32 + 255) / 256, 256>>>(W_h);
    prep_wo_kernel<<<(NS_A * 16 * 32 + 255) / 256, 256>>>(W_o);
    prep_wi_kernel<<<(NS_B * 16 * 32 + 255) / 256, 256>>>(W_i);

    int grid_bin = (N_BONDS + 63) / 64;   // 3438
    binput_mma_kernel<<<grid_bin, 256, BINM_SMEM>>>(fbonds);

    __half* src = msgA;
    __half* dst = msgB;
    int grid_mma = (N_BONDS + BMT - 1) / BMT;   // 3438
    for (int it = 0; it < 5; it++) {            // DEPTH-1
        bond_mma_kernel<<<grid_mma, 512, BOND_SMEM>>>(
            src, dst + (size_t)N_MESS * H, bgraph);
        __half* t = src; src = dst; dst = t;
    }

    int grid_a = (N_ATOMS + 63) / 64;           // 1563
    atom_mma_kernel<<<grid_a, 256, ATOM_SMEM>>>(src, agraph, fatoms, b_o);

    pool_kernel<<<N_MOLS, H>>>(mol_ids, (float*)d_out);
}